// round 1
// baseline (speedup 1.0000x reference)
#include <cuda_runtime.h>
#include <cuda_bf16.h>

// Problem dims (fixed by the dataset)
#define BB 8
#define SS 2048
#define DD 1024
#define HH 1024
#define LL 4
#define MM (BB * SS)     // 16384
#define N2H (2 * HH)     // 2048
#define KK DD            // 1024 (== HH for layers >= 1)

// Scratch: device globals (allocation is banned)
__device__ float g_gh[(size_t)MM * N2H];    // 134 MB: GEMM output (gate|hidden)
__device__ float g_buf0[(size_t)MM * HH];   // 67 MB: layer activations ping
__device__ float g_buf1[(size_t)MM * HH];   // 67 MB: layer activations pong

// ---------------------------------------------------------------------------
// GEMM: C[m, e] = sum_d A[m, d] * W[e, d] + bias[e]
// A: (M, K) row-major, W: (N, K) row-major (i.e. both K-contiguous)
// Tile: 128x128, BK=16, 256 threads, 8x8 per thread.
// ---------------------------------------------------------------------------
#define BM 128
#define BN 128
#define BK 16

__global__ __launch_bounds__(256) void gemm_bias_kernel(
    const float* __restrict__ A, const float* __restrict__ W,
    const float* __restrict__ bias, float* __restrict__ C)
{
    __shared__ __align__(16) float As[BK][BM + 4];
    __shared__ __align__(16) float Bs[BK][BN + 4];

    const int tid  = threadIdx.x;
    const int row0 = blockIdx.y * BM;
    const int col0 = blockIdx.x * BN;

    // loader indices: each thread loads 2 float4 from A and 2 from W per K-tile
    const int lr = tid >> 2;          // 0..63
    const int lc = (tid & 3) * 4;     // 0,4,8,12

    // compute indices: 16x16 thread grid; rows {tr*4+i, 64+tr*4+i}, cols {tc*4+j, 64+tc*4+j}
    const int tr = tid >> 4;          // 0..15
    const int tc = tid & 15;          // 0..15

    const float* Aptr = A + (size_t)row0 * KK;
    const float* Wptr = W + (size_t)col0 * KK;

    float acc[8][8];
#pragma unroll
    for (int i = 0; i < 8; i++)
#pragma unroll
        for (int j = 0; j < 8; j++) acc[i][j] = 0.0f;

    for (int kt = 0; kt < KK; kt += BK) {
#pragma unroll
        for (int half = 0; half < 2; half++) {
            const int r = lr + half * 64;
            float4 va = *(const float4*)(Aptr + (size_t)r * KK + kt + lc);
            As[lc + 0][r] = va.x; As[lc + 1][r] = va.y;
            As[lc + 2][r] = va.z; As[lc + 3][r] = va.w;
            float4 vb = *(const float4*)(Wptr + (size_t)r * KK + kt + lc);
            Bs[lc + 0][r] = vb.x; Bs[lc + 1][r] = vb.y;
            Bs[lc + 2][r] = vb.z; Bs[lc + 3][r] = vb.w;
        }
        __syncthreads();

#pragma unroll
        for (int kk = 0; kk < BK; kk++) {
            float a[8], b[8];
            *(float4*)(a + 0) = *(const float4*)&As[kk][tr * 4];
            *(float4*)(a + 4) = *(const float4*)&As[kk][64 + tr * 4];
            *(float4*)(b + 0) = *(const float4*)&Bs[kk][tc * 4];
            *(float4*)(b + 4) = *(const float4*)&Bs[kk][64 + tc * 4];
#pragma unroll
            for (int i = 0; i < 8; i++)
#pragma unroll
                for (int j = 0; j < 8; j++)
                    acc[i][j] = fmaf(a[i], b[j], acc[i][j]);
        }
        __syncthreads();
    }

    // epilogue with bias
    float bj[8];
#pragma unroll
    for (int j = 0; j < 4; j++) {
        bj[j]     = bias[col0 + tc * 4 + j];
        bj[4 + j] = bias[col0 + 64 + tc * 4 + j];
    }
#pragma unroll
    for (int ih = 0; ih < 2; ih++) {
#pragma unroll
        for (int i = 0; i < 4; i++) {
            const int r = row0 + ih * 64 + tr * 4 + i;
            float* crow = C + (size_t)r * N2H + col0;
#pragma unroll
            for (int jh = 0; jh < 2; jh++) {
                float4 v;
                v.x = acc[ih * 4 + i][jh * 4 + 0] + bj[jh * 4 + 0];
                v.y = acc[ih * 4 + i][jh * 4 + 1] + bj[jh * 4 + 1];
                v.z = acc[ih * 4 + i][jh * 4 + 2] + bj[jh * 4 + 2];
                v.w = acc[ih * 4 + i][jh * 4 + 3] + bj[jh * 4 + 3];
                *(float4*)(crow + jh * 64 + tc * 4) = v;
            }
        }
    }
}

// ---------------------------------------------------------------------------
// Scan: h_t = (1-z_t) h_{t-1} + z_t g(hid_t), z = sigmoid(gate), plus residual.
// One thread per (b, h) channel. gh layout: [b*S+s][2H] = gate(0:H) | hidden(H:2H)
// out[b,s,h] = h_t + inp[b,s,h];  finals[t] = h_{S-1} (pre-residual)
// ---------------------------------------------------------------------------
__device__ __forceinline__ float fast_sigmoid(float x) {
    return __fdividef(1.0f, 1.0f + __expf(-x));
}

__global__ __launch_bounds__(128) void scan_kernel(
    const float* __restrict__ gh, const float* __restrict__ inp,
    const float* __restrict__ hprev, float* __restrict__ out,
    float* __restrict__ finals)
{
    const int t  = blockIdx.x * blockDim.x + threadIdx.x;  // 0..B*H-1
    const int b  = t >> 10;
    const int hh = t & 1023;

    float hp = hprev[t];
    float h  = (hp >= 0.0f) ? (hp + 0.5f) : fast_sigmoid(hp);

    const float* ghp = gh  + (size_t)b * SS * N2H + hh;
    const float* ip  = inp + (size_t)b * SS * HH + hh;
    float*       op  = out + (size_t)b * SS * HH + hh;

#pragma unroll 8
    for (int s = 0; s < SS; s++) {
        const float gate = ghp[(size_t)s * N2H];
        const float hid  = ghp[(size_t)s * N2H + HH];
        const float xin  = ip[(size_t)s * HH];
        const float z    = fast_sigmoid(gate);
        const float gx   = (hid >= 0.0f) ? (hid + 0.5f) : fast_sigmoid(hid);
        h = h + z * (gx - h);
        op[(size_t)s * HH] = h + xin;
    }
    finals[t] = h;  // pre-residual last state
}

// ---------------------------------------------------------------------------
// Launch
// ---------------------------------------------------------------------------
extern "C" void kernel_launch(void* const* d_in, const int* in_sizes, int n_in,
                              void* d_out, int out_size)
{
    const float* x  = (const float*)d_in[0];  // (B,S,D)
    const float* h0 = (const float*)d_in[1];  // (L,B,1,H)
    const float* W0 = (const float*)d_in[2];  // (2H,D)
    const float* b0 = (const float*)d_in[3];  // (2H,)
    const float* Wl = (const float*)d_in[4];  // (L-1,2H,H)
    const float* bl = (const float*)d_in[5];  // (L-1,2H)

    float* out    = (float*)d_out;                 // (B,S,H) = M*H floats
    float* finals = out + (size_t)MM * HH;         // (L,B,1,H)

    float *gh, *buf0, *buf1;
    cudaGetSymbolAddress((void**)&gh,   g_gh);
    cudaGetSymbolAddress((void**)&buf0, g_buf0);
    cudaGetSymbolAddress((void**)&buf1, g_buf1);

    const dim3 ggrid(N2H / BN, MM / BM);   // (16, 128)
    const int scan_blocks = (BB * HH) / 128;  // 64

    const float* in_ptr = x;
    float* bufs[2] = {buf0, buf1};

    for (int l = 0; l < LL; l++) {
        const float* W = (l == 0) ? W0 : (Wl + (size_t)(l - 1) * N2H * HH);
        const float* bb = (l == 0) ? b0 : (bl + (size_t)(l - 1) * N2H);

        gemm_bias_kernel<<<ggrid, 256>>>(in_ptr, W, bb, gh);

        float* o = (l == LL - 1) ? out : bufs[l & 1];
        scan_kernel<<<scan_blocks, 128>>>(gh, in_ptr, h0 + (size_t)l * BB * HH,
                                          o, finals + (size_t)l * BB * HH);
        in_ptr = o;
    }
}

// round 3
// speedup vs baseline: 1.6526x; 1.6526x over previous
#include <cuda_runtime.h>
#include <cuda_bf16.h>
#include <cstdint>

// ---------------- problem dims ----------------
#define BB 8
#define SS 2048
#define HH 1024
#define LL 4
#define MM (BB * SS)       // 16384
#define N2H (2 * HH)       // 2048
#define KK 1024

// scan chunking
#define NC 32
#define CS (SS / NC)       // 64
#define NCH (BB * HH)      // 8192

// GEMM tiling
#define BM 128
#define BN 128
#define BK 32
#define NKIT (KK / BK)     // 32
#define BKP 40             // padded SMEM row stride in bf16 (80 bytes)

#define MAT_B (BM * BKP * 2)            // 10240 bytes per matrix tile
#define STAGE_B (4 * MAT_B)             // Ahi, Alo, Bhi, Blo = 40960
#define SMEM_TOTAL (2 * STAGE_B)        // 81920

// ---------------- scratch (device globals; allocation banned) ----------------
__device__ float          g_gh  [(size_t)MM * N2H];
__device__ float          g_buf0[(size_t)MM * HH];
__device__ float          g_buf1[(size_t)MM * HH];
__device__ __nv_bfloat16  g_ahi [(size_t)MM * KK];
__device__ __nv_bfloat16  g_alo [(size_t)MM * KK];
__device__ __nv_bfloat16  g_whi [(size_t)LL * N2H * KK];
__device__ __nv_bfloat16  g_wlo [(size_t)LL * N2H * KK];
__device__ float          g_C   [(size_t)NC * NCH];
__device__ float          g_V   [(size_t)NC * NCH];
__device__ float          g_hin [(size_t)NC * NCH];

// ---------------- PTX helpers (baseline sm_103 features only) ----------------
__device__ __forceinline__ uint32_t smem_u32(const void* p) {
    uint32_t a;
    asm("{ .reg .u64 t; cvta.to.shared.u64 t, %1; cvt.u32.u64 %0, t; }"
        : "=r"(a) : "l"(p));
    return a;
}
__device__ __forceinline__ void cp16(uint32_t s, const void* g) {
    asm volatile("cp.async.cg.shared.global [%0], [%1], 16;" :: "r"(s), "l"(g));
}
__device__ __forceinline__ void cp_commit() {
    asm volatile("cp.async.commit_group;" ::: "memory");
}
template <int N>
__device__ __forceinline__ void cp_wait() {
    asm volatile("cp.async.wait_group %0;" :: "n"(N) : "memory");
}
__device__ __forceinline__ void ldsm4(uint32_t* r, uint32_t addr) {
    asm volatile("ldmatrix.sync.aligned.m8n8.x4.shared.b16 {%0,%1,%2,%3}, [%4];"
                 : "=r"(r[0]), "=r"(r[1]), "=r"(r[2]), "=r"(r[3]) : "r"(addr));
}
__device__ __forceinline__ void mma16816(float* c, const uint32_t* a, const uint32_t* b) {
    asm volatile(
        "mma.sync.aligned.m16n8k16.row.col.f32.bf16.bf16.f32 "
        "{%0,%1,%2,%3}, {%4,%5,%6,%7}, {%8,%9}, {%0,%1,%2,%3};"
        : "+f"(c[0]), "+f"(c[1]), "+f"(c[2]), "+f"(c[3])
        : "r"(a[0]), "r"(a[1]), "r"(a[2]), "r"(a[3]), "r"(b[0]), "r"(b[1]));
}

// ---------------- fp32 -> bf16 hi/lo split ----------------
__global__ __launch_bounds__(256) void split_kernel(
    const float4* __restrict__ in, uint2* __restrict__ hi, uint2* __restrict__ lo, int n4)
{
    int i = blockIdx.x * blockDim.x + threadIdx.x;
    if (i >= n4) return;
    float4 v = in[i];
    __nv_bfloat16 h0 = __float2bfloat16(v.x), h1 = __float2bfloat16(v.y);
    __nv_bfloat16 h2 = __float2bfloat16(v.z), h3 = __float2bfloat16(v.w);
    __nv_bfloat16 l0 = __float2bfloat16(v.x - __bfloat162float(h0));
    __nv_bfloat16 l1 = __float2bfloat16(v.y - __bfloat162float(h1));
    __nv_bfloat16 l2 = __float2bfloat16(v.z - __bfloat162float(h2));
    __nv_bfloat16 l3 = __float2bfloat16(v.w - __bfloat162float(h3));
    uint2 H, L;
    H.x = (uint32_t)__bfloat16_as_ushort(h0) | ((uint32_t)__bfloat16_as_ushort(h1) << 16);
    H.y = (uint32_t)__bfloat16_as_ushort(h2) | ((uint32_t)__bfloat16_as_ushort(h3) << 16);
    L.x = (uint32_t)__bfloat16_as_ushort(l0) | ((uint32_t)__bfloat16_as_ushort(l1) << 16);
    L.y = (uint32_t)__bfloat16_as_ushort(l2) | ((uint32_t)__bfloat16_as_ushort(l3) << 16);
    hi[i] = H; lo[i] = L;
}

// ---------------- mma.sync GEMM: C = A * W^T + bias (bf16 hi/lo 3-split) ----
// A (M,K), W (N,K) both K-contiguous bf16 hi/lo; C (M, N2H) fp32.
// CTA tile 128x128, BK=32, 8 warps (4M x 2N), warp tile 32x64, 2-stage cp.async.
__global__ __launch_bounds__(256) void gemm_mma(
    const __nv_bfloat16* __restrict__ Ahi, const __nv_bfloat16* __restrict__ Alo,
    const __nv_bfloat16* __restrict__ Whi, const __nv_bfloat16* __restrict__ Wlo,
    const float* __restrict__ bias, float* __restrict__ C)
{
    extern __shared__ __align__(16) char smem[];
    const uint32_t sbase = smem_u32(smem);

    const int tid = threadIdx.x;
    const int wid = tid >> 5;
    const int lane = tid & 31;
    const int wm = wid & 3;        // M quarter (rows wm*32)
    const int wn = wid >> 2;       // N half   (cols wn*64)
    const int row0 = blockIdx.y * BM;
    const int col0 = blockIdx.x * BN;

    const __nv_bfloat16* Ah = Ahi + (size_t)row0 * KK;
    const __nv_bfloat16* Al = Alo + (size_t)row0 * KK;
    const __nv_bfloat16* Wh = Whi + (size_t)col0 * KK;
    const __nv_bfloat16* Wl = Wlo + (size_t)col0 * KK;

    // loader: each matrix tile = 128 rows x 64B = 512 x 16B chunks; 2 per thread
    auto load_stage = [&](int kt, int s) {
        const uint32_t st = sbase + s * STAGE_B;
        const int kof = kt * BK;
#pragma unroll
        for (int j = 0; j < 2; j++) {
            const int i = tid + 256 * j;
            const int r = i >> 2, c = i & 3;
            const uint32_t so = (uint32_t)(r * 80 + c * 16);
            const size_t go = (size_t)r * KK + kof + c * 8;
            cp16(st + 0 * MAT_B + so, Ah + go);
            cp16(st + 1 * MAT_B + so, Al + go);
            cp16(st + 2 * MAT_B + so, Wh + go);
            cp16(st + 3 * MAT_B + so, Wl + go);
        }
        cp_commit();
    };

    float acc[2][8][4];
#pragma unroll
    for (int t = 0; t < 2; t++)
#pragma unroll
        for (int n = 0; n < 8; n++)
#pragma unroll
            for (int q = 0; q < 4; q++) acc[t][n][q] = 0.0f;

    // ldmatrix lane addressing (byte offsets within a matrix tile)
    // A tile t (m16), kstep: lanes 0-7 rows0-7@k0, 8-15 rows8-15@k0,
    //                        16-23 rows0-7@k8, 24-31 rows8-15@k8
    const int arow = ((lane >> 3) & 1) * 8 + (lane & 7);
    const int akof = (lane >> 4) * 16;            // bytes
    // B pair p (n16), kstep: lanes 0-7 n0-7@k0, 8-15 n0-7@k8,
    //                        16-23 n8-15@k0, 24-31 n8-15@k8
    const int brow = ((lane >> 4) & 1) * 8 + (lane & 7);
    const int bkof = ((lane >> 3) & 1) * 16;      // bytes

    load_stage(0, 0);

    for (int kt = 0; kt < NKIT; kt++) {
        if (kt + 1 < NKIT) { load_stage(kt + 1, (kt + 1) & 1); cp_wait<1>(); }
        else               { cp_wait<0>(); }
        __syncthreads();

        const uint32_t st = sbase + (kt & 1) * STAGE_B;
        const uint32_t aH = st + 0 * MAT_B;
        const uint32_t aL = st + 1 * MAT_B;
        const uint32_t bH = st + 2 * MAT_B;
        const uint32_t bL = st + 3 * MAT_B;

#pragma unroll
        for (int ks = 0; ks < 2; ks++) {
            const int kb = ks * 32;   // byte offset of this k16 within the row
            uint32_t ar[2][4], br[8][2];

            // A hi
#pragma unroll
            for (int t = 0; t < 2; t++)
                ldsm4(ar[t], aH + (uint32_t)((wm * 32 + t * 16 + arow) * 80 + kb + akof));
            // B hi + mma hi*hi
#pragma unroll
            for (int p = 0; p < 4; p++) {
                uint32_t r4[4];
                ldsm4(r4, bH + (uint32_t)((wn * 64 + p * 16 + brow) * 80 + kb + bkof));
                br[2 * p][0] = r4[0]; br[2 * p][1] = r4[1];
                br[2 * p + 1][0] = r4[2]; br[2 * p + 1][1] = r4[3];
            }
#pragma unroll
            for (int t = 0; t < 2; t++)
#pragma unroll
                for (int n = 0; n < 8; n++) mma16816(acc[t][n], ar[t], br[n]);

            // B lo + mma hi*lo
#pragma unroll
            for (int p = 0; p < 4; p++) {
                uint32_t r4[4];
                ldsm4(r4, bL + (uint32_t)((wn * 64 + p * 16 + brow) * 80 + kb + bkof));
                br[2 * p][0] = r4[0]; br[2 * p][1] = r4[1];
                br[2 * p + 1][0] = r4[2]; br[2 * p + 1][1] = r4[3];
            }
#pragma unroll
            for (int t = 0; t < 2; t++)
#pragma unroll
                for (int n = 0; n < 8; n++) mma16816(acc[t][n], ar[t], br[n]);

            // A lo + reload B hi + mma lo*hi
#pragma unroll
            for (int t = 0; t < 2; t++)
                ldsm4(ar[t], aL + (uint32_t)((wm * 32 + t * 16 + arow) * 80 + kb + akof));
#pragma unroll
            for (int p = 0; p < 4; p++) {
                uint32_t r4[4];
                ldsm4(r4, bH + (uint32_t)((wn * 64 + p * 16 + brow) * 80 + kb + bkof));
                br[2 * p][0] = r4[0]; br[2 * p][1] = r4[1];
                br[2 * p + 1][0] = r4[2]; br[2 * p + 1][1] = r4[3];
            }
#pragma unroll
            for (int t = 0; t < 2; t++)
#pragma unroll
                for (int n = 0; n < 8; n++) mma16816(acc[t][n], ar[t], br[n]);
        }
        __syncthreads();
    }

    // epilogue: c0,c1 -> (row, col..col+1); c2,c3 -> (row+8, col..col+1)
    const int erow = row0 + wm * 32 + (lane >> 2);
    const int ecol0 = col0 + wn * 64 + 2 * (lane & 3);
#pragma unroll
    for (int t = 0; t < 2; t++) {
#pragma unroll
        for (int n = 0; n < 8; n++) {
            const int col = ecol0 + n * 8;
            const float2 bv = *(const float2*)(bias + col);
            float2 v0, v1;
            v0.x = acc[t][n][0] + bv.x; v0.y = acc[t][n][1] + bv.y;
            v1.x = acc[t][n][2] + bv.x; v1.y = acc[t][n][3] + bv.y;
            *(float2*)(C + (size_t)(erow + t * 16) * N2H + col) = v0;
            *(float2*)(C + (size_t)(erow + t * 16 + 8) * N2H + col) = v1;
        }
    }
}

// ---------------- scan ----------------
__device__ __forceinline__ void gate_cd(float gate, float hid, float& c, float& d) {
    const float t = __expf(-gate);
    const float inv = __fdividef(1.0f, 1.0f + t);
    c = t * inv;                  // 1 - sigmoid(gate)
    const float gx = (hid >= 0.0f) ? (hid + 0.5f)
                                   : __fdividef(1.0f, 1.0f + __expf(-hid));
    d = inv * gx;                 // sigmoid(gate) * g(hid)
}

// pass 1: per (channel, chunk): C = prod c, V = value with h_in = 0
__global__ __launch_bounds__(128) void scan1_kernel(
    const float* __restrict__ gh, float* __restrict__ Co, float* __restrict__ Vo)
{
    const int idx = blockIdx.x * blockDim.x + threadIdx.x;  // NCH*NC
    const int hh = idx & (HH - 1);
    const int rest = idx >> 10;
    const int chunk = rest & (NC - 1);
    const int b = rest >> 5;

    const float* g = gh + (size_t)(b * SS + chunk * CS) * N2H + hh;
    float Ca = 1.0f, Va = 0.0f;
#pragma unroll 4
    for (int s = 0; s < CS; s++) {
        float c, d;
        gate_cd(g[(size_t)s * N2H], g[(size_t)s * N2H + HH], c, d);
        Ca *= c;
        Va = c * Va + d;
    }
    const int ch = b * HH + hh;
    Co[chunk * NCH + ch] = Ca;
    Vo[chunk * NCH + ch] = Va;
}

// pass 2: per channel: scan over chunks, emit per-chunk h_in + finals
__global__ __launch_bounds__(128) void scan2_kernel(
    const float* __restrict__ Co, const float* __restrict__ Vo,
    const float* __restrict__ hprev, float* __restrict__ hin,
    float* __restrict__ finals)
{
    const int ch = blockIdx.x * blockDim.x + threadIdx.x;  // 0..NCH-1
    const float hp = hprev[ch];
    float h = (hp >= 0.0f) ? (hp + 0.5f) : __fdividef(1.0f, 1.0f + __expf(-hp));
#pragma unroll
    for (int k = 0; k < NC; k++) {
        hin[k * NCH + ch] = h;
        h = Co[k * NCH + ch] * h + Vo[k * NCH + ch];
    }
    finals[ch] = h;
}

// pass 3: recompute with correct h_in, add residual, write fp32 out (+ hi/lo)
__global__ __launch_bounds__(128) void scan3_kernel(
    const float* __restrict__ gh, const float* __restrict__ inp,
    const float* __restrict__ hin, float* __restrict__ out,
    __nv_bfloat16* __restrict__ ohi, __nv_bfloat16* __restrict__ olo)
{
    const int idx = blockIdx.x * blockDim.x + threadIdx.x;
    const int hh = idx & (HH - 1);
    const int rest = idx >> 10;
    const int chunk = rest & (NC - 1);
    const int b = rest >> 5;
    const int ch = b * HH + hh;

    const size_t base2h = (size_t)(b * SS + chunk * CS) * N2H + hh;
    const size_t base1h = (size_t)(b * SS + chunk * CS) * HH + hh;
    const float* g = gh + base2h;
    const float* ip = inp + base1h;
    float* op = out + base1h;

    float h = hin[chunk * NCH + ch];
#pragma unroll 4
    for (int s = 0; s < CS; s++) {
        float c, d;
        gate_cd(g[(size_t)s * N2H], g[(size_t)s * N2H + HH], c, d);
        h = c * h + d;
        const float o = h + ip[(size_t)s * HH];
        op[(size_t)s * HH] = o;
        if (ohi) {
            const __nv_bfloat16 hb = __float2bfloat16(o);
            ohi[base1h + (size_t)s * HH] = hb;
            olo[base1h + (size_t)s * HH] = __float2bfloat16(o - __bfloat162float(hb));
        }
    }
}

// ---------------- launch ----------------
extern "C" void kernel_launch(void* const* d_in, const int* in_sizes, int n_in,
                              void* d_out, int out_size)
{
    const float* x  = (const float*)d_in[0];  // (B,S,D)
    const float* h0 = (const float*)d_in[1];  // (L,B,1,H)
    const float* W0 = (const float*)d_in[2];  // (2H,D)
    const float* b0 = (const float*)d_in[3];  // (2H,)
    const float* Wl = (const float*)d_in[4];  // (L-1,2H,H)
    const float* bl = (const float*)d_in[5];  // (L-1,2H)

    float* out    = (float*)d_out;
    float* finals = out + (size_t)MM * HH;

    float *gh, *buf0, *buf1, *Cb, *Vb, *hinb;
    __nv_bfloat16 *ahi, *alo, *whi, *wlo;
    cudaGetSymbolAddress((void**)&gh,   g_gh);
    cudaGetSymbolAddress((void**)&buf0, g_buf0);
    cudaGetSymbolAddress((void**)&buf1, g_buf1);
    cudaGetSymbolAddress((void**)&ahi,  g_ahi);
    cudaGetSymbolAddress((void**)&alo,  g_alo);
    cudaGetSymbolAddress((void**)&whi,  g_whi);
    cudaGetSymbolAddress((void**)&wlo,  g_wlo);
    cudaGetSymbolAddress((void**)&Cb,   g_C);
    cudaGetSymbolAddress((void**)&Vb,   g_V);
    cudaGetSymbolAddress((void**)&hinb, g_hin);

    cudaFuncSetAttribute(gemm_mma, cudaFuncAttributeMaxDynamicSharedMemorySize, SMEM_TOTAL);

    // layer-0 input + all weights -> bf16 hi/lo
    {
        int n4 = (MM * KK) / 4;
        split_kernel<<<(n4 + 255) / 256, 256>>>((const float4*)x, (uint2*)ahi, (uint2*)alo, n4);
        n4 = (N2H * KK) / 4;
        split_kernel<<<(n4 + 255) / 256, 256>>>((const float4*)W0, (uint2*)whi, (uint2*)wlo, n4);
        n4 = (3 * N2H * KK) / 4;
        split_kernel<<<(n4 + 255) / 256, 256>>>((const float4*)Wl,
                                                (uint2*)(whi + (size_t)N2H * KK),
                                                (uint2*)(wlo + (size_t)N2H * KK), n4);
    }

    const dim3 ggrid(N2H / BN, MM / BM);           // (16, 128)
    const int scan13_blocks = (NCH * NC) / 128;    // 2048
    const int scan2_blocks = NCH / 128;            // 64

    const float* in_ptr = x;
    float* fbufs[3] = {buf0, buf1, buf0};

    for (int l = 0; l < LL; l++) {
        const __nv_bfloat16* Whl = whi + (size_t)l * N2H * KK;
        const __nv_bfloat16* Wll = wlo + (size_t)l * N2H * KK;
        const float* bb = (l == 0) ? b0 : (bl + (size_t)(l - 1) * N2H);

        gemm_mma<<<ggrid, 256, SMEM_TOTAL>>>(ahi, alo, Whl, Wll, bb, gh);

        scan1_kernel<<<scan13_blocks, 128>>>(gh, Cb, Vb);
        scan2_kernel<<<scan2_blocks, 128>>>(Cb, Vb, h0 + (size_t)l * NCH, hinb,
                                            finals + (size_t)l * NCH);

        float* o = (l == LL - 1) ? out : fbufs[l];
        __nv_bfloat16* nhi = (l == LL - 1) ? nullptr : ahi;
        __nv_bfloat16* nlo = (l == LL - 1) ? nullptr : alo;
        scan3_kernel<<<scan13_blocks, 128>>>(gh, in_ptr, hinb, o, nhi, nlo);
        in_ptr = o;
    }
}

// round 4
// speedup vs baseline: 2.8773x; 1.7410x over previous
#include <cuda_runtime.h>
#include <cuda_bf16.h>
#include <cstdint>

// ---------------- problem dims ----------------
#define BB 8
#define SS 2048
#define HH 1024
#define LL 4
#define MM (BB * SS)       // 16384
#define N2H (2 * HH)       // 2048
#define KK 1024

// scan chunking
#define NC 32
#define CS (SS / NC)       // 64
#define NCH (BB * HH)      // 8192

// GEMM tiling
#define BM 128
#define BN 128
#define BK 32
#define NKIT (KK / BK)     // 32

#define MAT_B (BM * 40 * 2)             // 10240 bytes per matrix tile (80B rows)
#define STAGE_B (4 * MAT_B)             // Ahi, Alo, Bhi, Blo = 40960
#define SMEM_TOTAL (2 * STAGE_B)        // 81920

// ---------------- scratch (device globals; allocation banned) ----------------
__device__ float          g_gh  [(size_t)MM * N2H];
__device__ float          g_buf0[(size_t)MM * HH];
__device__ float          g_buf1[(size_t)MM * HH];
__device__ __nv_bfloat16  g_ahi [(size_t)MM * KK];
__device__ __nv_bfloat16  g_alo [(size_t)MM * KK];
__device__ __nv_bfloat16  g_whi [(size_t)LL * N2H * KK];
__device__ __nv_bfloat16  g_wlo [(size_t)LL * N2H * KK];
__device__ float          g_C   [(size_t)NC * NCH];
__device__ float          g_V   [(size_t)NC * NCH];
__device__ float          g_hin [(size_t)NC * NCH];

// ---------------- PTX helpers (baseline sm_103 features only) ----------------
__device__ __forceinline__ uint32_t smem_u32(const void* p) {
    uint32_t a;
    asm("{ .reg .u64 t; cvta.to.shared.u64 t, %1; cvt.u32.u64 %0, t; }"
        : "=r"(a) : "l"(p));
    return a;
}
__device__ __forceinline__ void cp16(uint32_t s, const void* g) {
    asm volatile("cp.async.cg.shared.global [%0], [%1], 16;" :: "r"(s), "l"(g));
}
__device__ __forceinline__ void cp_commit() {
    asm volatile("cp.async.commit_group;" ::: "memory");
}
template <int N>
__device__ __forceinline__ void cp_wait() {
    asm volatile("cp.async.wait_group %0;" :: "n"(N) : "memory");
}
__device__ __forceinline__ void ldsm4(uint32_t* r, uint32_t addr) {
    asm volatile("ldmatrix.sync.aligned.m8n8.x4.shared.b16 {%0,%1,%2,%3}, [%4];"
                 : "=r"(r[0]), "=r"(r[1]), "=r"(r[2]), "=r"(r[3]) : "r"(addr));
}
__device__ __forceinline__ void mma16816(float* c, const uint32_t* a, const uint32_t* b) {
    asm volatile(
        "mma.sync.aligned.m16n8k16.row.col.f32.bf16.bf16.f32 "
        "{%0,%1,%2,%3}, {%4,%5,%6,%7}, {%8,%9}, {%0,%1,%2,%3};"
        : "+f"(c[0]), "+f"(c[1]), "+f"(c[2]), "+f"(c[3])
        : "r"(a[0]), "r"(a[1]), "r"(a[2]), "r"(a[3]), "r"(b[0]), "r"(b[1]));
}

// ---------------- fp32 -> bf16 hi/lo split ----------------
__global__ __launch_bounds__(256) void split_kernel(
    const float4* __restrict__ in, uint2* __restrict__ hi, uint2* __restrict__ lo, int n4)
{
    int i = blockIdx.x * blockDim.x + threadIdx.x;
    if (i >= n4) return;
    float4 v = in[i];
    __nv_bfloat16 h0 = __float2bfloat16(v.x), h1 = __float2bfloat16(v.y);
    __nv_bfloat16 h2 = __float2bfloat16(v.z), h3 = __float2bfloat16(v.w);
    __nv_bfloat16 l0 = __float2bfloat16(v.x - __bfloat162float(h0));
    __nv_bfloat16 l1 = __float2bfloat16(v.y - __bfloat162float(h1));
    __nv_bfloat16 l2 = __float2bfloat16(v.z - __bfloat162float(h2));
    __nv_bfloat16 l3 = __float2bfloat16(v.w - __bfloat162float(h3));
    uint2 H, L;
    H.x = (uint32_t)__bfloat16_as_ushort(h0) | ((uint32_t)__bfloat16_as_ushort(h1) << 16);
    H.y = (uint32_t)__bfloat16_as_ushort(h2) | ((uint32_t)__bfloat16_as_ushort(h3) << 16);
    L.x = (uint32_t)__bfloat16_as_ushort(l0) | ((uint32_t)__bfloat16_as_ushort(l1) << 16);
    L.y = (uint32_t)__bfloat16_as_ushort(l2) | ((uint32_t)__bfloat16_as_ushort(l3) << 16);
    hi[i] = H; lo[i] = L;
}

// ---------------- mma.sync GEMM: C = A * W^T + bias (bf16 hi/lo 3-split) ----
// CTA tile 128x128, BK=32, 8 warps (4M x 2N), warp tile 32x64, 2-stage cp.async.
// min 2 blocks/SM: reg cap -> second resident CTA hides sync/load bubbles.
__global__ __launch_bounds__(256, 2) void gemm_mma(
    const __nv_bfloat16* __restrict__ Ahi, const __nv_bfloat16* __restrict__ Alo,
    const __nv_bfloat16* __restrict__ Whi, const __nv_bfloat16* __restrict__ Wlo,
    const float* __restrict__ bias, float* __restrict__ C)
{
    extern __shared__ __align__(16) char smem[];
    const uint32_t sbase = smem_u32(smem);

    const int tid = threadIdx.x;
    const int wid = tid >> 5;
    const int lane = tid & 31;
    const int wm = wid & 3;        // M quarter (rows wm*32)
    const int wn = wid >> 2;       // N half   (cols wn*64)
    const int row0 = blockIdx.y * BM;
    const int col0 = blockIdx.x * BN;

    const __nv_bfloat16* Ah = Ahi + (size_t)row0 * KK;
    const __nv_bfloat16* Al = Alo + (size_t)row0 * KK;
    const __nv_bfloat16* Wh = Whi + (size_t)col0 * KK;
    const __nv_bfloat16* Wl = Wlo + (size_t)col0 * KK;

    // loader: each matrix tile = 128 rows x 64B = 512 x 16B chunks; 2 per thread
    auto load_stage = [&](int kt, int s) {
        const uint32_t st = sbase + s * STAGE_B;
        const int kof = kt * BK;
#pragma unroll
        for (int j = 0; j < 2; j++) {
            const int i = tid + 256 * j;
            const int r = i >> 2, c = i & 3;
            const uint32_t so = (uint32_t)(r * 80 + c * 16);
            const size_t go = (size_t)r * KK + kof + c * 8;
            cp16(st + 0 * MAT_B + so, Ah + go);
            cp16(st + 1 * MAT_B + so, Al + go);
            cp16(st + 2 * MAT_B + so, Wh + go);
            cp16(st + 3 * MAT_B + so, Wl + go);
        }
        cp_commit();
    };

    float acc[2][8][4];
#pragma unroll
    for (int t = 0; t < 2; t++)
#pragma unroll
        for (int n = 0; n < 8; n++)
#pragma unroll
            for (int q = 0; q < 4; q++) acc[t][n][q] = 0.0f;

    // ldmatrix lane addressing (byte offsets within a matrix tile)
    const int arow = ((lane >> 3) & 1) * 8 + (lane & 7);
    const int akof = (lane >> 4) * 16;            // bytes
    const int brow = ((lane >> 4) & 1) * 8 + (lane & 7);
    const int bkof = ((lane >> 3) & 1) * 16;      // bytes

    load_stage(0, 0);

    for (int kt = 0; kt < NKIT; kt++) {
        if (kt + 1 < NKIT) { load_stage(kt + 1, (kt + 1) & 1); cp_wait<1>(); }
        else               { cp_wait<0>(); }
        __syncthreads();

        const uint32_t st = sbase + (kt & 1) * STAGE_B;
        const uint32_t aH = st + 0 * MAT_B;
        const uint32_t aL = st + 1 * MAT_B;
        const uint32_t bH = st + 2 * MAT_B;
        const uint32_t bL = st + 3 * MAT_B;

#pragma unroll
        for (int ks = 0; ks < 2; ks++) {
            const int kb = ks * 32;   // byte offset of this k16 within the row
            uint32_t ah[2][4], al[2][4];

            // A hi + A lo up front (8 ldsm-regs each)
#pragma unroll
            for (int t = 0; t < 2; t++) {
                ldsm4(ah[t], aH + (uint32_t)((wm * 32 + t * 16 + arow) * 80 + kb + akof));
                ldsm4(al[t], aL + (uint32_t)((wm * 32 + t * 16 + arow) * 80 + kb + akof));
            }

            // B hi pass: hi*hi and lo*hi while the fragment is live
#pragma unroll
            for (int p = 0; p < 4; p++) {
                uint32_t r4[4];
                ldsm4(r4, bH + (uint32_t)((wn * 64 + p * 16 + brow) * 80 + kb + bkof));
#pragma unroll
                for (int t = 0; t < 2; t++) {
                    mma16816(acc[t][2 * p],     ah[t], r4);
                    mma16816(acc[t][2 * p + 1], ah[t], r4 + 2);
                    mma16816(acc[t][2 * p],     al[t], r4);
                    mma16816(acc[t][2 * p + 1], al[t], r4 + 2);
                }
            }
            // B lo pass: hi*lo
#pragma unroll
            for (int p = 0; p < 4; p++) {
                uint32_t r4[4];
                ldsm4(r4, bL + (uint32_t)((wn * 64 + p * 16 + brow) * 80 + kb + bkof));
#pragma unroll
                for (int t = 0; t < 2; t++) {
                    mma16816(acc[t][2 * p],     ah[t], r4);
                    mma16816(acc[t][2 * p + 1], ah[t], r4 + 2);
                }
            }
        }
        __syncthreads();
    }

    // epilogue: c0,c1 -> (row, col..col+1); c2,c3 -> (row+8, col..col+1)
    const int erow = row0 + wm * 32 + (lane >> 2);
    const int ecol0 = col0 + wn * 64 + 2 * (lane & 3);
#pragma unroll
    for (int t = 0; t < 2; t++) {
#pragma unroll
        for (int n = 0; n < 8; n++) {
            const int col = ecol0 + n * 8;
            const float2 bv = *(const float2*)(bias + col);
            float2 v0, v1;
            v0.x = acc[t][n][0] + bv.x; v0.y = acc[t][n][1] + bv.y;
            v1.x = acc[t][n][2] + bv.x; v1.y = acc[t][n][3] + bv.y;
            *(float2*)(C + (size_t)(erow + t * 16) * N2H + col) = v0;
            *(float2*)(C + (size_t)(erow + t * 16 + 8) * N2H + col) = v1;
        }
    }
}

// ---------------- scan ----------------
__device__ __forceinline__ void gate_cd(float gate, float hid, float& c, float& d) {
    const float t = __expf(-gate);
    const float inv = __fdividef(1.0f, 1.0f + t);
    c = t * inv;                  // 1 - sigmoid(gate)
    const float gx = (hid >= 0.0f) ? (hid + 0.5f)
                                   : __fdividef(1.0f, 1.0f + __expf(-hid));
    d = inv * gx;                 // sigmoid(gate) * g(hid)
}

// pass 1: per (channel, chunk): C = prod c, V = value with h_in = 0
__global__ __launch_bounds__(128) void scan1_kernel(
    const float* __restrict__ gh, float* __restrict__ Co, float* __restrict__ Vo)
{
    const int idx = blockIdx.x * blockDim.x + threadIdx.x;  // NCH*NC
    const int hh = idx & (HH - 1);
    const int rest = idx >> 10;
    const int chunk = rest & (NC - 1);
    const int b = rest >> 5;

    const float* g = gh + (size_t)(b * SS + chunk * CS) * N2H + hh;
    float Ca = 1.0f, Va = 0.0f;
#pragma unroll 4
    for (int s = 0; s < CS; s++) {
        float c, d;
        gate_cd(g[(size_t)s * N2H], g[(size_t)s * N2H + HH], c, d);
        Ca *= c;
        Va = c * Va + d;
    }
    const int ch = b * HH + hh;
    Co[chunk * NCH + ch] = Ca;
    Vo[chunk * NCH + ch] = Va;
}

// pass 2: per channel: scan over chunks, emit per-chunk h_in + finals
__global__ __launch_bounds__(128) void scan2_kernel(
    const float* __restrict__ Co, const float* __restrict__ Vo,
    const float* __restrict__ hprev, float* __restrict__ hin,
    float* __restrict__ finals)
{
    const int ch = blockIdx.x * blockDim.x + threadIdx.x;  // 0..NCH-1
    const float hp = hprev[ch];
    float h = (hp >= 0.0f) ? (hp + 0.5f) : __fdividef(1.0f, 1.0f + __expf(-hp));
#pragma unroll
    for (int k = 0; k < NC; k++) {
        hin[k * NCH + ch] = h;
        h = Co[k * NCH + ch] * h + Vo[k * NCH + ch];
    }
    finals[ch] = h;
}

// pass 3: recompute with correct h_in, add residual, write fp32 out (+ hi/lo)
__global__ __launch_bounds__(128) void scan3_kernel(
    const float* __restrict__ gh, const float* __restrict__ inp,
    const float* __restrict__ hin, float* __restrict__ out,
    __nv_bfloat16* __restrict__ ohi, __nv_bfloat16* __restrict__ olo)
{
    const int idx = blockIdx.x * blockDim.x + threadIdx.x;
    const int hh = idx & (HH - 1);
    const int rest = idx >> 10;
    const int chunk = rest & (NC - 1);
    const int b = rest >> 5;
    const int ch = b * HH + hh;

    const size_t base2h = (size_t)(b * SS + chunk * CS) * N2H + hh;
    const size_t base1h = (size_t)(b * SS + chunk * CS) * HH + hh;
    const float* g = gh + base2h;
    const float* ip = inp + base1h;
    float* op = out + base1h;

    float h = hin[chunk * NCH + ch];
#pragma unroll 4
    for (int s = 0; s < CS; s++) {
        float c, d;
        gate_cd(g[(size_t)s * N2H], g[(size_t)s * N2H + HH], c, d);
        h = c * h + d;
        const float o = h + ip[(size_t)s * HH];
        op[(size_t)s * HH] = o;
        if (ohi) {
            const __nv_bfloat16 hb = __float2bfloat16(o);
            ohi[base1h + (size_t)s * HH] = hb;
            olo[base1h + (size_t)s * HH] = __float2bfloat16(o - __bfloat162float(hb));
        }
    }
}

// ---------------- launch ----------------
extern "C" void kernel_launch(void* const* d_in, const int* in_sizes, int n_in,
                              void* d_out, int out_size)
{
    const float* x  = (const float*)d_in[0];  // (B,S,D)
    const float* h0 = (const float*)d_in[1];  // (L,B,1,H)
    const float* W0 = (const float*)d_in[2];  // (2H,D)
    const float* b0 = (const float*)d_in[3];  // (2H,)
    const float* Wl = (const float*)d_in[4];  // (L-1,2H,H)
    const float* bl = (const float*)d_in[5];  // (L-1,2H)

    float* out    = (float*)d_out;
    float* finals = out + (size_t)MM * HH;

    float *gh, *buf0, *buf1, *Cb, *Vb, *hinb;
    __nv_bfloat16 *ahi, *alo, *whi, *wlo;
    cudaGetSymbolAddress((void**)&gh,   g_gh);
    cudaGetSymbolAddress((void**)&buf0, g_buf0);
    cudaGetSymbolAddress((void**)&buf1, g_buf1);
    cudaGetSymbolAddress((void**)&ahi,  g_ahi);
    cudaGetSymbolAddress((void**)&alo,  g_alo);
    cudaGetSymbolAddress((void**)&whi,  g_whi);
    cudaGetSymbolAddress((void**)&wlo,  g_wlo);
    cudaGetSymbolAddress((void**)&Cb,   g_C);
    cudaGetSymbolAddress((void**)&Vb,   g_V);
    cudaGetSymbolAddress((void**)&hinb, g_hin);

    cudaFuncSetAttribute(gemm_mma, cudaFuncAttributeMaxDynamicSharedMemorySize, SMEM_TOTAL);

    // layer-0 input + all weights -> bf16 hi/lo
    {
        int n4 = (MM * KK) / 4;
        split_kernel<<<(n4 + 255) / 256, 256>>>((const float4*)x, (uint2*)ahi, (uint2*)alo, n4);
        n4 = (N2H * KK) / 4;
        split_kernel<<<(n4 + 255) / 256, 256>>>((const float4*)W0, (uint2*)whi, (uint2*)wlo, n4);
        n4 = (3 * N2H * KK) / 4;
        split_kernel<<<(n4 + 255) / 256, 256>>>((const float4*)Wl,
                                                (uint2*)(whi + (size_t)N2H * KK),
                                                (uint2*)(wlo + (size_t)N2H * KK), n4);
    }

    const dim3 ggrid(N2H / BN, MM / BM);           // (16, 128)
    const int scan13_blocks = (NCH * NC) / 128;    // 2048
    const int scan2_blocks = NCH / 128;            // 64

    const float* in_ptr = x;
    float* fbufs[3] = {buf0, buf1, buf0};

    for (int l = 0; l < LL; l++) {
        const __nv_bfloat16* Whl = whi + (size_t)l * N2H * KK;
        const __nv_bfloat16* Wll = wlo + (size_t)l * N2H * KK;
        const float* bb = (l == 0) ? b0 : (bl + (size_t)(l - 1) * N2H);

        gemm_mma<<<ggrid, 256, SMEM_TOTAL>>>(ahi, alo, Whl, Wll, bb, gh);

        scan1_kernel<<<scan13_blocks, 128>>>(gh, Cb, Vb);
        scan2_kernel<<<scan2_blocks, 128>>>(Cb, Vb, h0 + (size_t)l * NCH, hinb,
                                            finals + (size_t)l * NCH);

        float* o = (l == LL - 1) ? out : fbufs[l];
        __nv_bfloat16* nhi = (l == LL - 1) ? nullptr : ahi;
        __nv_bfloat16* nlo = (l == LL - 1) ? nullptr : alo;
        scan3_kernel<<<scan13_blocks, 128>>>(gh, in_ptr, hinb, o, nhi, nlo);
        in_ptr = o;
    }
}

// round 5
// speedup vs baseline: 3.0901x; 1.0740x over previous
#include <cuda_runtime.h>
#include <cuda_bf16.h>
#include <cstdint>

// ---------------- problem dims ----------------
#define BB 8
#define SS 2048
#define HH 1024
#define LL 4
#define MM (BB * SS)       // 16384
#define N2H (2 * HH)       // 2048
#define KK 1024

// scan chunking
#define NC 32
#define CS (SS / NC)       // 64
#define NCH (BB * HH)      // 8192

// GEMM tiling
#define BM 128
#define BN 128
#define BK 32
#define NKIT (KK / BK)     // 32

#define MAT_B (BM * 64)                 // 8192 bytes per matrix tile (64B rows, swizzled)
#define STAGE_B (4 * MAT_B)             // Ahi, Alo, Bhi, Blo = 32768
#define NSTAGE 3
#define SMEM_TOTAL (NSTAGE * STAGE_B)   // 98304 -> 2 CTAs/SM (196KB <= 227KB)

// SW64-style swizzle: rows at 64B stride, XOR bits[5:4] with bits[8:7] (row>>1 & 3).
// Makes ldmatrix 8-row phases hit 8 distinct 16B bank-quads.
#define SWZ(off) ((off) ^ (((off) >> 3) & 0x30))

// ---------------- scratch (device globals; allocation banned) ----------------
__device__ float          g_gh  [(size_t)MM * N2H];
__device__ float          g_buf0[(size_t)MM * HH];
__device__ float          g_buf1[(size_t)MM * HH];
__device__ __nv_bfloat16  g_ahi [(size_t)MM * KK];
__device__ __nv_bfloat16  g_alo [(size_t)MM * KK];
__device__ __nv_bfloat16  g_whi [(size_t)LL * N2H * KK];
__device__ __nv_bfloat16  g_wlo [(size_t)LL * N2H * KK];
__device__ float          g_C   [(size_t)NC * NCH];
__device__ float          g_V   [(size_t)NC * NCH];
__device__ float          g_hin [(size_t)NC * NCH];

// ---------------- PTX helpers (baseline sm_103 features only) ----------------
__device__ __forceinline__ uint32_t smem_u32(const void* p) {
    uint32_t a;
    asm("{ .reg .u64 t; cvta.to.shared.u64 t, %1; cvt.u32.u64 %0, t; }"
        : "=r"(a) : "l"(p));
    return a;
}
__device__ __forceinline__ void cp16(uint32_t s, const void* g) {
    asm volatile("cp.async.cg.shared.global [%0], [%1], 16;" :: "r"(s), "l"(g));
}
__device__ __forceinline__ void cp_commit() {
    asm volatile("cp.async.commit_group;" ::: "memory");
}
template <int N>
__device__ __forceinline__ void cp_wait() {
    asm volatile("cp.async.wait_group %0;" :: "n"(N) : "memory");
}
__device__ __forceinline__ void ldsm4(uint32_t* r, uint32_t addr) {
    asm volatile("ldmatrix.sync.aligned.m8n8.x4.shared.b16 {%0,%1,%2,%3}, [%4];"
                 : "=r"(r[0]), "=r"(r[1]), "=r"(r[2]), "=r"(r[3]) : "r"(addr));
}
__device__ __forceinline__ void mma16816(float* c, const uint32_t* a, const uint32_t* b) {
    asm volatile(
        "mma.sync.aligned.m16n8k16.row.col.f32.bf16.bf16.f32 "
        "{%0,%1,%2,%3}, {%4,%5,%6,%7}, {%8,%9}, {%0,%1,%2,%3};"
        : "+f"(c[0]), "+f"(c[1]), "+f"(c[2]), "+f"(c[3])
        : "r"(a[0]), "r"(a[1]), "r"(a[2]), "r"(a[3]), "r"(b[0]), "r"(b[1]));
}

// ---------------- fp32 -> bf16 hi/lo split ----------------
__global__ __launch_bounds__(256) void split_kernel(
    const float4* __restrict__ in, uint2* __restrict__ hi, uint2* __restrict__ lo, int n4)
{
    int i = blockIdx.x * blockDim.x + threadIdx.x;
    if (i >= n4) return;
    float4 v = in[i];
    __nv_bfloat16 h0 = __float2bfloat16(v.x), h1 = __float2bfloat16(v.y);
    __nv_bfloat16 h2 = __float2bfloat16(v.z), h3 = __float2bfloat16(v.w);
    __nv_bfloat16 l0 = __float2bfloat16(v.x - __bfloat162float(h0));
    __nv_bfloat16 l1 = __float2bfloat16(v.y - __bfloat162float(h1));
    __nv_bfloat16 l2 = __float2bfloat16(v.z - __bfloat162float(h2));
    __nv_bfloat16 l3 = __float2bfloat16(v.w - __bfloat162float(h3));
    uint2 H, L;
    H.x = (uint32_t)__bfloat16_as_ushort(h0) | ((uint32_t)__bfloat16_as_ushort(h1) << 16);
    H.y = (uint32_t)__bfloat16_as_ushort(h2) | ((uint32_t)__bfloat16_as_ushort(h3) << 16);
    L.x = (uint32_t)__bfloat16_as_ushort(l0) | ((uint32_t)__bfloat16_as_ushort(l1) << 16);
    L.y = (uint32_t)__bfloat16_as_ushort(l2) | ((uint32_t)__bfloat16_as_ushort(l3) << 16);
    hi[i] = H; lo[i] = L;
}

// ---------------- mma.sync GEMM: C = A * W^T + bias (bf16 hi/lo 3-split) ----
// CTA tile 128x128, BK=32, 8 warps (4M x 2N), warp tile 32x64.
// 3-stage cp.async ring (prefetch depth 2, ONE barrier per K-iter), swizzled
// 64B-row tiles, min 2 blocks/SM.
__global__ __launch_bounds__(256, 2) void gemm_mma(
    const __nv_bfloat16* __restrict__ Ahi, const __nv_bfloat16* __restrict__ Alo,
    const __nv_bfloat16* __restrict__ Whi, const __nv_bfloat16* __restrict__ Wlo,
    const float* __restrict__ bias, float* __restrict__ C)
{
    extern __shared__ __align__(1024) char smem[];
    const uint32_t sbase = smem_u32(smem);

    const int tid = threadIdx.x;
    const int wid = tid >> 5;
    const int lane = tid & 31;
    const int wm = wid & 3;        // M quarter (rows wm*32)
    const int wn = wid >> 2;       // N half   (cols wn*64)
    const int row0 = blockIdx.y * BM;
    const int col0 = blockIdx.x * BN;

    const __nv_bfloat16* Ah = Ahi + (size_t)row0 * KK;
    const __nv_bfloat16* Al = Alo + (size_t)row0 * KK;
    const __nv_bfloat16* Wh = Whi + (size_t)col0 * KK;
    const __nv_bfloat16* Wl = Wlo + (size_t)col0 * KK;

    // loader: each matrix tile = 128 rows x 64B = 512 x 16B chunks; 2 per thread
    auto load_stage = [&](int kt, int s) {
        const uint32_t st = sbase + s * STAGE_B;
        const int kof = kt * BK;
#pragma unroll
        for (int j = 0; j < 2; j++) {
            const int i = tid + 256 * j;
            const int r = i >> 2, c = i & 3;
            const uint32_t so = SWZ((uint32_t)(r * 64 + c * 16));
            const size_t go = (size_t)r * KK + kof + c * 8;
            cp16(st + 0 * MAT_B + so, Ah + go);
            cp16(st + 1 * MAT_B + so, Al + go);
            cp16(st + 2 * MAT_B + so, Wh + go);
            cp16(st + 3 * MAT_B + so, Wl + go);
        }
        cp_commit();
    };

    float acc[2][8][4];
#pragma unroll
    for (int t = 0; t < 2; t++)
#pragma unroll
        for (int n = 0; n < 8; n++)
#pragma unroll
            for (int q = 0; q < 4; q++) acc[t][n][q] = 0.0f;

    // ldmatrix lane addressing (byte offsets within a matrix tile, pre-swizzle)
    const int arow = ((lane >> 3) & 1) * 8 + (lane & 7);
    const int akof = (lane >> 4) * 16;            // bytes
    const int brow = ((lane >> 4) & 1) * 8 + (lane & 7);
    const int bkof = ((lane >> 3) & 1) * 16;      // bytes

    load_stage(0, 0);
    load_stage(1, 1);

    for (int kt = 0; kt < NKIT; kt++) {
        cp_wait<1>();
        __syncthreads();

        if (kt + 2 < NKIT) {
            int s = kt + 2; while (s >= NSTAGE) s -= NSTAGE;
            load_stage(kt + 2, s);
        }

        int cs = kt; while (cs >= NSTAGE) cs -= NSTAGE;
        const uint32_t st = sbase + cs * STAGE_B;
        const uint32_t aH = st + 0 * MAT_B;
        const uint32_t aL = st + 1 * MAT_B;
        const uint32_t bH = st + 2 * MAT_B;
        const uint32_t bL = st + 3 * MAT_B;

#pragma unroll
        for (int ks = 0; ks < 2; ks++) {
            const int kb = ks * 32;   // byte offset of this k16 within the row
            uint32_t ah[2][4], al[2][4];

            // A hi + A lo up front
#pragma unroll
            for (int t = 0; t < 2; t++) {
                const uint32_t off = (uint32_t)((wm * 32 + t * 16 + arow) * 64 + kb + akof);
                ldsm4(ah[t], aH + SWZ(off));
                ldsm4(al[t], aL + SWZ(off));
            }

            // B hi pass: hi*hi and lo*hi while the fragment is live
#pragma unroll
            for (int p = 0; p < 4; p++) {
                uint32_t r4[4];
                const uint32_t off = (uint32_t)((wn * 64 + p * 16 + brow) * 64 + kb + bkof);
                ldsm4(r4, bH + SWZ(off));
#pragma unroll
                for (int t = 0; t < 2; t++) {
                    mma16816(acc[t][2 * p],     ah[t], r4);
                    mma16816(acc[t][2 * p + 1], ah[t], r4 + 2);
                    mma16816(acc[t][2 * p],     al[t], r4);
                    mma16816(acc[t][2 * p + 1], al[t], r4 + 2);
                }
            }
            // B lo pass: hi*lo
#pragma unroll
            for (int p = 0; p < 4; p++) {
                uint32_t r4[4];
                const uint32_t off = (uint32_t)((wn * 64 + p * 16 + brow) * 64 + kb + bkof);
                ldsm4(r4, bL + SWZ(off));
#pragma unroll
                for (int t = 0; t < 2; t++) {
                    mma16816(acc[t][2 * p],     ah[t], r4);
                    mma16816(acc[t][2 * p + 1], ah[t], r4 + 2);
                }
            }
        }
    }

    // epilogue: c0,c1 -> (row, col..col+1); c2,c3 -> (row+8, col..col+1)
    const int erow = row0 + wm * 32 + (lane >> 2);
    const int ecol0 = col0 + wn * 64 + 2 * (lane & 3);
#pragma unroll
    for (int t = 0; t < 2; t++) {
#pragma unroll
        for (int n = 0; n < 8; n++) {
            const int col = ecol0 + n * 8;
            const float2 bv = *(const float2*)(bias + col);
            float2 v0, v1;
            v0.x = acc[t][n][0] + bv.x; v0.y = acc[t][n][1] + bv.y;
            v1.x = acc[t][n][2] + bv.x; v1.y = acc[t][n][3] + bv.y;
            *(float2*)(C + (size_t)(erow + t * 16) * N2H + col) = v0;
            *(float2*)(C + (size_t)(erow + t * 16 + 8) * N2H + col) = v1;
        }
    }
}

// ---------------- scan ----------------
__device__ __forceinline__ void gate_cd(float gate, float hid, float& c, float& d) {
    const float t = __expf(-gate);
    const float inv = __fdividef(1.0f, 1.0f + t);
    c = t * inv;                  // 1 - sigmoid(gate)
    const float gx = (hid >= 0.0f) ? (hid + 0.5f)
                                   : __fdividef(1.0f, 1.0f + __expf(-hid));
    d = inv * gx;                 // sigmoid(gate) * g(hid)
}

// pass 1: per (channel, chunk): C = prod c, V = value with h_in = 0
__global__ __launch_bounds__(128) void scan1_kernel(
    const float* __restrict__ gh, float* __restrict__ Co, float* __restrict__ Vo)
{
    const int idx = blockIdx.x * blockDim.x + threadIdx.x;  // NCH*NC
    const int hh = idx & (HH - 1);
    const int rest = idx >> 10;
    const int chunk = rest & (NC - 1);
    const int b = rest >> 5;

    const float* g = gh + (size_t)(b * SS + chunk * CS) * N2H + hh;
    float Ca = 1.0f, Va = 0.0f;
#pragma unroll 4
    for (int s = 0; s < CS; s++) {
        float c, d;
        gate_cd(g[(size_t)s * N2H], g[(size_t)s * N2H + HH], c, d);
        Ca *= c;
        Va = c * Va + d;
    }
    const int ch = b * HH + hh;
    Co[chunk * NCH + ch] = Ca;
    Vo[chunk * NCH + ch] = Va;
}

// pass 2: per channel: scan over chunks, emit per-chunk h_in + finals
__global__ __launch_bounds__(128) void scan2_kernel(
    const float* __restrict__ Co, const float* __restrict__ Vo,
    const float* __restrict__ hprev, float* __restrict__ hin,
    float* __restrict__ finals)
{
    const int ch = blockIdx.x * blockDim.x + threadIdx.x;  // 0..NCH-1
    const float hp = hprev[ch];
    float h = (hp >= 0.0f) ? (hp + 0.5f) : __fdividef(1.0f, 1.0f + __expf(-hp));
#pragma unroll
    for (int k = 0; k < NC; k++) {
        hin[k * NCH + ch] = h;
        h = Co[k * NCH + ch] * h + Vo[k * NCH + ch];
    }
    finals[ch] = h;
}

// pass 3: recompute with correct h_in, add residual, write fp32 out (+ hi/lo)
__global__ __launch_bounds__(128) void scan3_kernel(
    const float* __restrict__ gh, const float* __restrict__ inp,
    const float* __restrict__ hin, float* __restrict__ out,
    __nv_bfloat16* __restrict__ ohi, __nv_bfloat16* __restrict__ olo)
{
    const int idx = blockIdx.x * blockDim.x + threadIdx.x;
    const int hh = idx & (HH - 1);
    const int rest = idx >> 10;
    const int chunk = rest & (NC - 1);
    const int b = rest >> 5;
    const int ch = b * HH + hh;

    const size_t base2h = (size_t)(b * SS + chunk * CS) * N2H + hh;
    const size_t base1h = (size_t)(b * SS + chunk * CS) * HH + hh;
    const float* g = gh + base2h;
    const float* ip = inp + base1h;
    float* op = out + base1h;

    float h = hin[chunk * NCH + ch];
#pragma unroll 4
    for (int s = 0; s < CS; s++) {
        float c, d;
        gate_cd(g[(size_t)s * N2H], g[(size_t)s * N2H + HH], c, d);
        h = c * h + d;
        const float o = h + ip[(size_t)s * HH];
        op[(size_t)s * HH] = o;
        if (ohi) {
            const __nv_bfloat16 hb = __float2bfloat16(o);
            ohi[base1h + (size_t)s * HH] = hb;
            olo[base1h + (size_t)s * HH] = __float2bfloat16(o - __bfloat162float(hb));
        }
    }
}

// ---------------- launch ----------------
extern "C" void kernel_launch(void* const* d_in, const int* in_sizes, int n_in,
                              void* d_out, int out_size)
{
    const float* x  = (const float*)d_in[0];  // (B,S,D)
    const float* h0 = (const float*)d_in[1];  // (L,B,1,H)
    const float* W0 = (const float*)d_in[2];  // (2H,D)
    const float* b0 = (const float*)d_in[3];  // (2H,)
    const float* Wl = (const float*)d_in[4];  // (L-1,2H,H)
    const float* bl = (const float*)d_in[5];  // (L-1,2H)

    float* out    = (float*)d_out;
    float* finals = out + (size_t)MM * HH;

    float *gh, *buf0, *buf1, *Cb, *Vb, *hinb;
    __nv_bfloat16 *ahi, *alo, *whi, *wlo;
    cudaGetSymbolAddress((void**)&gh,   g_gh);
    cudaGetSymbolAddress((void**)&buf0, g_buf0);
    cudaGetSymbolAddress((void**)&buf1, g_buf1);
    cudaGetSymbolAddress((void**)&ahi,  g_ahi);
    cudaGetSymbolAddress((void**)&alo,  g_alo);
    cudaGetSymbolAddress((void**)&whi,  g_whi);
    cudaGetSymbolAddress((void**)&wlo,  g_wlo);
    cudaGetSymbolAddress((void**)&Cb,   g_C);
    cudaGetSymbolAddress((void**)&Vb,   g_V);
    cudaGetSymbolAddress((void**)&hinb, g_hin);

    cudaFuncSetAttribute(gemm_mma, cudaFuncAttributeMaxDynamicSharedMemorySize, SMEM_TOTAL);

    // layer-0 input + all weights -> bf16 hi/lo
    {
        int n4 = (MM * KK) / 4;
        split_kernel<<<(n4 + 255) / 256, 256>>>((const float4*)x, (uint2*)ahi, (uint2*)alo, n4);
        n4 = (N2H * KK) / 4;
        split_kernel<<<(n4 + 255) / 256, 256>>>((const float4*)W0, (uint2*)whi, (uint2*)wlo, n4);
        n4 = (3 * N2H * KK) / 4;
        split_kernel<<<(n4 + 255) / 256, 256>>>((const float4*)Wl,
                                                (uint2*)(whi + (size_t)N2H * KK),
                                                (uint2*)(wlo + (size_t)N2H * KK), n4);
    }

    const dim3 ggrid(N2H / BN, MM / BM);           // (16, 128)
    const int scan13_blocks = (NCH * NC) / 128;    // 2048
    const int scan2_blocks = NCH / 128;            // 64

    const float* in_ptr = x;
    float* fbufs[3] = {buf0, buf1, buf0};

    for (int l = 0; l < LL; l++) {
        const __nv_bfloat16* Whl = whi + (size_t)l * N2H * KK;
        const __nv_bfloat16* Wll = wlo + (size_t)l * N2H * KK;
        const float* bb = (l == 0) ? b0 : (bl + (size_t)(l - 1) * N2H);

        gemm_mma<<<ggrid, 256, SMEM_TOTAL>>>(ahi, alo, Whl, Wll, bb, gh);

        scan1_kernel<<<scan13_blocks, 128>>>(gh, Cb, Vb);
        scan2_kernel<<<scan2_blocks, 128>>>(Cb, Vb, h0 + (size_t)l * NCH, hinb,
                                            finals + (size_t)l * NCH);

        float* o = (l == LL - 1) ? out : fbufs[l];
        __nv_bfloat16* nhi = (l == LL - 1) ? nullptr : ahi;
        __nv_bfloat16* nlo = (l == LL - 1) ? nullptr : alo;
        scan3_kernel<<<scan13_blocks, 128>>>(gh, in_ptr, hinb, o, nhi, nlo);
        in_ptr = o;
    }
}

// round 6
// speedup vs baseline: 3.2271x; 1.0444x over previous
#include <cuda_runtime.h>
#include <cuda_bf16.h>
#include <cstdint>

// ---------------- problem dims ----------------
#define BB 8
#define SS 2048
#define HH 1024
#define LL 4
#define MM (BB * SS)       // 16384
#define N2H (2 * HH)       // 2048
#define KK 1024

// scan chunking
#define NC 32
#define CS (SS / NC)       // 64
#define NCH (BB * HH)      // 8192

// GEMM tiling
#define BM 128
#define BN 128
#define BK 32
#define NKIT (KK / BK)     // 32

#define MAT_B (BM * 64)                 // 8192 bytes per matrix tile (64B rows, swizzled)
#define STAGE_B (4 * MAT_B)             // Ahi, Alo, Bhi, Blo = 32768
#define NSTAGE 3
#define SMEM_TOTAL (NSTAGE * STAGE_B)   // 98304 -> 2 CTAs/SM

// SW64-style swizzle: XOR bits[5:4] with bits[8:7]
#define SWZ(off) ((off) ^ (((off) >> 3) & 0x30))

// ---------------- scratch (device globals; allocation banned) ----------------
__device__ float          g_gh  [(size_t)MM * N2H];
__device__ __nv_bfloat16  g_ahi [(size_t)MM * KK];
__device__ __nv_bfloat16  g_alo [(size_t)MM * KK];
__device__ __nv_bfloat16  g_whi [(size_t)LL * N2H * KK];
__device__ __nv_bfloat16  g_wlo [(size_t)LL * N2H * KK];
__device__ float          g_C   [(size_t)NC * NCH];
__device__ float          g_V   [(size_t)NC * NCH];
__device__ float          g_hin [(size_t)NC * NCH];

// ---------------- PTX helpers (baseline sm_103 features only) ----------------
__device__ __forceinline__ uint32_t smem_u32(const void* p) {
    uint32_t a;
    asm("{ .reg .u64 t; cvta.to.shared.u64 t, %1; cvt.u32.u64 %0, t; }"
        : "=r"(a) : "l"(p));
    return a;
}
__device__ __forceinline__ void cp16(uint32_t s, const void* g) {
    asm volatile("cp.async.cg.shared.global [%0], [%1], 16;" :: "r"(s), "l"(g));
}
__device__ __forceinline__ void cp_commit() {
    asm volatile("cp.async.commit_group;" ::: "memory");
}
template <int N>
__device__ __forceinline__ void cp_wait() {
    asm volatile("cp.async.wait_group %0;" :: "n"(N) : "memory");
}
__device__ __forceinline__ void ldsm4(uint32_t* r, uint32_t addr) {
    asm volatile("ldmatrix.sync.aligned.m8n8.x4.shared.b16 {%0,%1,%2,%3}, [%4];"
                 : "=r"(r[0]), "=r"(r[1]), "=r"(r[2]), "=r"(r[3]) : "r"(addr));
}
__device__ __forceinline__ void mma16816(float* c, const uint32_t* a, const uint32_t* b) {
    asm volatile(
        "mma.sync.aligned.m16n8k16.row.col.f32.bf16.bf16.f32 "
        "{%0,%1,%2,%3}, {%4,%5,%6,%7}, {%8,%9}, {%0,%1,%2,%3};"
        : "+f"(c[0]), "+f"(c[1]), "+f"(c[2]), "+f"(c[3])
        : "r"(a[0]), "r"(a[1]), "r"(a[2]), "r"(a[3]), "r"(b[0]), "r"(b[1]));
}

// ---------------- fp32 -> bf16 hi/lo split ----------------
__global__ __launch_bounds__(256) void split_kernel(
    const float4* __restrict__ in, uint2* __restrict__ hi, uint2* __restrict__ lo, int n4)
{
    int i = blockIdx.x * blockDim.x + threadIdx.x;
    if (i >= n4) return;
    float4 v = in[i];
    __nv_bfloat16 h0 = __float2bfloat16(v.x), h1 = __float2bfloat16(v.y);
    __nv_bfloat16 h2 = __float2bfloat16(v.z), h3 = __float2bfloat16(v.w);
    __nv_bfloat16 l0 = __float2bfloat16(v.x - __bfloat162float(h0));
    __nv_bfloat16 l1 = __float2bfloat16(v.y - __bfloat162float(h1));
    __nv_bfloat16 l2 = __float2bfloat16(v.z - __bfloat162float(h2));
    __nv_bfloat16 l3 = __float2bfloat16(v.w - __bfloat162float(h3));
    uint2 H, L;
    H.x = (uint32_t)__bfloat16_as_ushort(h0) | ((uint32_t)__bfloat16_as_ushort(h1) << 16);
    H.y = (uint32_t)__bfloat16_as_ushort(h2) | ((uint32_t)__bfloat16_as_ushort(h3) << 16);
    L.x = (uint32_t)__bfloat16_as_ushort(l0) | ((uint32_t)__bfloat16_as_ushort(l1) << 16);
    L.y = (uint32_t)__bfloat16_as_ushort(l2) | ((uint32_t)__bfloat16_as_ushort(l3) << 16);
    hi[i] = H; lo[i] = L;
}

// ---------------- mma.sync GEMM: C = A * W^T + bias (bf16 hi/lo 3-split) ----
// CTA 128x128, BK=32, 8 warps (4M x 2N), warp tile 32x64, 3-stage cp.async ring,
// swizzled 64B rows, precomputed smem offsets, B-fragment software pipeline.
__global__ __launch_bounds__(256, 2) void gemm_mma(
    const __nv_bfloat16* __restrict__ Ahi, const __nv_bfloat16* __restrict__ Alo,
    const __nv_bfloat16* __restrict__ Whi, const __nv_bfloat16* __restrict__ Wlo,
    const float* __restrict__ bias, float* __restrict__ C)
{
    extern __shared__ __align__(1024) char smem[];
    const uint32_t sbase = smem_u32(smem);

    const int tid = threadIdx.x;
    const int wid = tid >> 5;
    const int lane = tid & 31;
    const int wm = wid & 3;
    const int wn = wid >> 2;
    const int row0 = blockIdx.y * BM;
    const int col0 = blockIdx.x * BN;

    const __nv_bfloat16* Ah = Ahi + (size_t)row0 * KK;
    const __nv_bfloat16* Al = Alo + (size_t)row0 * KK;
    const __nv_bfloat16* Wh = Whi + (size_t)col0 * KK;
    const __nv_bfloat16* Wl = Wlo + (size_t)col0 * KK;

    auto load_stage = [&](int kt, int s) {
        const uint32_t st = sbase + s * STAGE_B;
        const int kof = kt * BK;
#pragma unroll
        for (int j = 0; j < 2; j++) {
            const int i = tid + 256 * j;
            const int r = i >> 2, c = i & 3;
            const uint32_t so = SWZ((uint32_t)(r * 64 + c * 16));
            const size_t go = (size_t)r * KK + kof + c * 8;
            cp16(st + 0 * MAT_B + so, Ah + go);
            cp16(st + 1 * MAT_B + so, Al + go);
            cp16(st + 2 * MAT_B + so, Wh + go);
            cp16(st + 3 * MAT_B + so, Wl + go);
        }
        cp_commit();
    };

    float acc[2][8][4];
#pragma unroll
    for (int t = 0; t < 2; t++)
#pragma unroll
        for (int n = 0; n < 8; n++)
#pragma unroll
            for (int q = 0; q < 4; q++) acc[t][n][q] = 0.0f;

    // precomputed swizzled byte offsets (within a matrix tile) for all ks/t/p
    const int arow = ((lane >> 3) & 1) * 8 + (lane & 7);
    const int akof = (lane >> 4) * 16;
    const int brow = ((lane >> 4) & 1) * 8 + (lane & 7);
    const int bkof = ((lane >> 3) & 1) * 16;

    uint32_t aoff[2][2], boff[2][4];
#pragma unroll
    for (int ks = 0; ks < 2; ks++) {
#pragma unroll
        for (int t = 0; t < 2; t++)
            aoff[ks][t] = SWZ((uint32_t)((wm * 32 + t * 16 + arow) * 64 + ks * 32 + akof));
#pragma unroll
        for (int p = 0; p < 4; p++)
            boff[ks][p] = SWZ((uint32_t)((wn * 64 + p * 16 + brow) * 64 + ks * 32 + bkof));
    }

    load_stage(0, 0);
    load_stage(1, 1);

    for (int kt = 0; kt < NKIT; kt++) {
        cp_wait<1>();
        __syncthreads();

        if (kt + 2 < NKIT) {
            int s = kt + 2; while (s >= NSTAGE) s -= NSTAGE;
            load_stage(kt + 2, s);
        }

        int cs = kt; while (cs >= NSTAGE) cs -= NSTAGE;
        const uint32_t st = sbase + cs * STAGE_B;
        const uint32_t aH = st + 0 * MAT_B;
        const uint32_t aL = st + 1 * MAT_B;
        const uint32_t bH = st + 2 * MAT_B;
        const uint32_t bL = st + 3 * MAT_B;

#pragma unroll
        for (int ks = 0; ks < 2; ks++) {
            uint32_t ah[2][4], al[2][4];
#pragma unroll
            for (int t = 0; t < 2; t++) {
                ldsm4(ah[t], aH + aoff[ks][t]);
                ldsm4(al[t], aL + aoff[ks][t]);
            }

            // B pipeline: two live fragments, ldsm(next) issued before mma(cur)
            uint32_t bf[2][4];
            ldsm4(bf[0], bH + boff[ks][0]);
#pragma unroll
            for (int p = 0; p < 4; p++) {
                if (p < 3) ldsm4(bf[(p + 1) & 1], bH + boff[ks][p + 1]);
                else       ldsm4(bf[(p + 1) & 1], bL + boff[ks][0]);
                const uint32_t* r4 = bf[p & 1];
#pragma unroll
                for (int t = 0; t < 2; t++) {
                    mma16816(acc[t][2 * p],     ah[t], r4);
                    mma16816(acc[t][2 * p + 1], ah[t], r4 + 2);
                    mma16816(acc[t][2 * p],     al[t], r4);
                    mma16816(acc[t][2 * p + 1], al[t], r4 + 2);
                }
            }
#pragma unroll
            for (int p = 0; p < 4; p++) {
                if (p < 3) ldsm4(bf[(p + 1) & 1], bL + boff[ks][p + 1]);
                const uint32_t* r4 = bf[p & 1];
#pragma unroll
                for (int t = 0; t < 2; t++) {
                    mma16816(acc[t][2 * p],     ah[t], r4);
                    mma16816(acc[t][2 * p + 1], ah[t], r4 + 2);
                }
            }
        }
    }

    const int erow = row0 + wm * 32 + (lane >> 2);
    const int ecol0 = col0 + wn * 64 + 2 * (lane & 3);
#pragma unroll
    for (int t = 0; t < 2; t++) {
#pragma unroll
        for (int n = 0; n < 8; n++) {
            const int col = ecol0 + n * 8;
            const float2 bv = *(const float2*)(bias + col);
            float2 v0, v1;
            v0.x = acc[t][n][0] + bv.x; v0.y = acc[t][n][1] + bv.y;
            v1.x = acc[t][n][2] + bv.x; v1.y = acc[t][n][3] + bv.y;
            *(float2*)(C + (size_t)(erow + t * 16) * N2H + col) = v0;
            *(float2*)(C + (size_t)(erow + t * 16 + 8) * N2H + col) = v1;
        }
    }
}

// ---------------- scan ----------------
__device__ __forceinline__ void gate_cd(float gate, float hid, float& c, float& d) {
    const float t = __expf(-gate);
    const float inv = __fdividef(1.0f, 1.0f + t);
    c = t * inv;                  // 1 - sigmoid(gate)
    const float gx = (hid >= 0.0f) ? (hid + 0.5f)
                                   : __fdividef(1.0f, 1.0f + __expf(-hid));
    d = inv * gx;                 // sigmoid(gate) * g(hid)
}

// pass 1: per (channel, chunk): C = prod c, V = value with h_in = 0
__global__ __launch_bounds__(128) void scan1_kernel(
    const float* __restrict__ gh, float* __restrict__ Co, float* __restrict__ Vo)
{
    const int idx = blockIdx.x * blockDim.x + threadIdx.x;
    const int hh = idx & (HH - 1);
    const int rest = idx >> 10;
    const int chunk = rest & (NC - 1);
    const int b = rest >> 5;

    const float* g = gh + (size_t)(b * SS + chunk * CS) * N2H + hh;
    float Ca = 1.0f, Va = 0.0f;
#pragma unroll 4
    for (int s = 0; s < CS; s++) {
        float c, d;
        gate_cd(g[(size_t)s * N2H], g[(size_t)s * N2H + HH], c, d);
        Ca *= c;
        Va = c * Va + d;
    }
    const int ch = b * HH + hh;
    Co[chunk * NCH + ch] = Ca;
    Vo[chunk * NCH + ch] = Va;
}

// pass 2: per channel: scan over chunks, emit per-chunk h_in + finals
__global__ __launch_bounds__(128) void scan2_kernel(
    const float* __restrict__ Co, const float* __restrict__ Vo,
    const float* __restrict__ hprev, float* __restrict__ hin,
    float* __restrict__ finals)
{
    const int ch = blockIdx.x * blockDim.x + threadIdx.x;
    const float hp = hprev[ch];
    float h = (hp >= 0.0f) ? (hp + 0.5f) : __fdividef(1.0f, 1.0f + __expf(-hp));
#pragma unroll
    for (int k = 0; k < NC; k++) {
        hin[k * NCH + ch] = h;
        h = Co[k * NCH + ch] * h + Vo[k * NCH + ch];
    }
    finals[ch] = h;
}

// pass 3: recompute with correct h_in; input read as bf16 hi/lo pair (x = hi+lo);
// residual add; write either next-layer hi/lo split IN PLACE, or final fp32 out.
__global__ __launch_bounds__(128) void scan3_kernel(
    const float* __restrict__ gh,
    __nv_bfloat16* __restrict__ ihi, __nv_bfloat16* __restrict__ ilo,
    const float* __restrict__ hin, float* __restrict__ outF)
{
    const int idx = blockIdx.x * blockDim.x + threadIdx.x;
    const int hh = idx & (HH - 1);
    const int rest = idx >> 10;
    const int chunk = rest & (NC - 1);
    const int b = rest >> 5;
    const int ch = b * HH + hh;

    const size_t base2h = (size_t)(b * SS + chunk * CS) * N2H + hh;
    const size_t base1h = (size_t)(b * SS + chunk * CS) * HH + hh;
    const float* g = gh + base2h;

    float h = hin[chunk * NCH + ch];
#pragma unroll 4
    for (int s = 0; s < CS; s++) {
        float c, d;
        gate_cd(g[(size_t)s * N2H], g[(size_t)s * N2H + HH], c, d);
        h = c * h + d;
        const size_t p = base1h + (size_t)s * HH;
        const float xin = __bfloat162float(ihi[p]) + __bfloat162float(ilo[p]);
        const float o = h + xin;
        if (outF) {
            outF[p] = o;
        } else {
            const __nv_bfloat16 hb = __float2bfloat16(o);
            ihi[p] = hb;
            ilo[p] = __float2bfloat16(o - __bfloat162float(hb));
        }
    }
}

// ---------------- launch ----------------
extern "C" void kernel_launch(void* const* d_in, const int* in_sizes, int n_in,
                              void* d_out, int out_size)
{
    const float* x  = (const float*)d_in[0];  // (B,S,D)
    const float* h0 = (const float*)d_in[1];  // (L,B,1,H)
    const float* W0 = (const float*)d_in[2];  // (2H,D)
    const float* b0 = (const float*)d_in[3];  // (2H,)
    const float* Wl = (const float*)d_in[4];  // (L-1,2H,H)
    const float* bl = (const float*)d_in[5];  // (L-1,2H)

    float* out    = (float*)d_out;
    float* finals = out + (size_t)MM * HH;

    float *gh, *Cb, *Vb, *hinb;
    __nv_bfloat16 *ahi, *alo, *whi, *wlo;
    cudaGetSymbolAddress((void**)&gh,   g_gh);
    cudaGetSymbolAddress((void**)&ahi,  g_ahi);
    cudaGetSymbolAddress((void**)&alo,  g_alo);
    cudaGetSymbolAddress((void**)&whi,  g_whi);
    cudaGetSymbolAddress((void**)&wlo,  g_wlo);
    cudaGetSymbolAddress((void**)&Cb,   g_C);
    cudaGetSymbolAddress((void**)&Vb,   g_V);
    cudaGetSymbolAddress((void**)&hinb, g_hin);

    cudaFuncSetAttribute(gemm_mma, cudaFuncAttributeMaxDynamicSharedMemorySize, SMEM_TOTAL);

    // layer-0 input + all weights -> bf16 hi/lo
    {
        int n4 = (MM * KK) / 4;
        split_kernel<<<(n4 + 255) / 256, 256>>>((const float4*)x, (uint2*)ahi, (uint2*)alo, n4);
        n4 = (N2H * KK) / 4;
        split_kernel<<<(n4 + 255) / 256, 256>>>((const float4*)W0, (uint2*)whi, (uint2*)wlo, n4);
        n4 = (3 * N2H * KK) / 4;
        split_kernel<<<(n4 + 255) / 256, 256>>>((const float4*)Wl,
                                                (uint2*)(whi + (size_t)N2H * KK),
                                                (uint2*)(wlo + (size_t)N2H * KK), n4);
    }

    const dim3 ggrid(N2H / BN, MM / BM);           // (16, 128)
    const int scan13_blocks = (NCH * NC) / 128;    // 2048
    const int scan2_blocks = NCH / 128;            // 64

    for (int l = 0; l < LL; l++) {
        const __nv_bfloat16* Whl = whi + (size_t)l * N2H * KK;
        const __nv_bfloat16* Wll = wlo + (size_t)l * N2H * KK;
        const float* bb = (l == 0) ? b0 : (bl + (size_t)(l - 1) * N2H);

        gemm_mma<<<ggrid, 256, SMEM_TOTAL>>>(ahi, alo, Whl, Wll, bb, gh);

        scan1_kernel<<<scan13_blocks, 128>>>(gh, Cb, Vb);
        scan2_kernel<<<scan2_blocks, 128>>>(Cb, Vb, h0 + (size_t)l * NCH, hinb,
                                            finals + (size_t)l * NCH);
        scan3_kernel<<<scan13_blocks, 128>>>(gh, ahi, alo, hinb,
                                             (l == LL - 1) ? out : nullptr);
    }
}

// round 8
// speedup vs baseline: 3.2286x; 1.0005x over previous
#include <cuda_runtime.h>
#include <cuda_bf16.h>
#include <cstdint>

// ---------------- problem dims ----------------
#define BB 8
#define SS 2048
#define HH 1024
#define LL 4
#define MM (BB * SS)       // 16384
#define N2H (2 * HH)       // 2048
#define KK 1024

// scan chunking
#define NC 32
#define CS (SS / NC)       // 64
#define NCH (BB * HH)      // 8192

// GEMM tiling
#define BM 128
#define BN 128
#define BK 32
#define NKIT (KK / BK)     // 32

#define MAT_B (BM * 64)                 // 8192 bytes per matrix tile (64B rows, swizzled)
#define STAGE_B (4 * MAT_B)             // Ahi, Alo, Bhi, Blo = 32768
#define NSTAGE 3
#define SMEM_TOTAL (NSTAGE * STAGE_B)   // 98304 -> 2 CTAs/SM

// SW64-style swizzle: XOR bits[5:4] with bits[8:7].
// Deltas at bit>=10 (p*1024, t*1024, MAT_B, STAGE_B) commute with SWZ on the
// swizzled address. k-step (+32) does NOT (swizzled bit5 may carry) -> use
// per-ks precomputed swizzled bases.
#define SWZ(off) ((off) ^ (((off) >> 3) & 0x30))

// ---------------- scratch (device globals; allocation banned) ----------------
__device__ float          g_gh  [(size_t)MM * N2H];
__device__ __nv_bfloat16  g_ahi [(size_t)MM * KK];
__device__ __nv_bfloat16  g_alo [(size_t)MM * KK];
__device__ __nv_bfloat16  g_whi [(size_t)LL * N2H * KK];
__device__ __nv_bfloat16  g_wlo [(size_t)LL * N2H * KK];
__device__ float          g_C   [(size_t)NC * NCH];
__device__ float          g_V   [(size_t)NC * NCH];
__device__ float          g_hin [(size_t)NC * NCH];

// ---------------- PTX helpers (baseline sm_103 features only) ----------------
__device__ __forceinline__ uint32_t smem_u32(const void* p) {
    uint32_t a;
    asm("{ .reg .u64 t; cvta.to.shared.u64 t, %1; cvt.u32.u64 %0, t; }"
        : "=r"(a) : "l"(p));
    return a;
}
__device__ __forceinline__ void cp16(uint32_t s, const void* g) {
    asm volatile("cp.async.cg.shared.global [%0], [%1], 16;" :: "r"(s), "l"(g));
}
__device__ __forceinline__ void cp_commit() {
    asm volatile("cp.async.commit_group;" ::: "memory");
}
template <int N>
__device__ __forceinline__ void cp_wait() {
    asm volatile("cp.async.wait_group %0;" :: "n"(N) : "memory");
}
__device__ __forceinline__ void ldsm4(uint32_t* r, uint32_t addr) {
    asm volatile("ldmatrix.sync.aligned.m8n8.x4.shared.b16 {%0,%1,%2,%3}, [%4];"
                 : "=r"(r[0]), "=r"(r[1]), "=r"(r[2]), "=r"(r[3]) : "r"(addr));
}
__device__ __forceinline__ void mma16816(float* c, const uint32_t* a, const uint32_t* b) {
    asm volatile(
        "mma.sync.aligned.m16n8k16.row.col.f32.bf16.bf16.f32 "
        "{%0,%1,%2,%3}, {%4,%5,%6,%7}, {%8,%9}, {%0,%1,%2,%3};"
        : "+f"(c[0]), "+f"(c[1]), "+f"(c[2]), "+f"(c[3])
        : "r"(a[0]), "r"(a[1]), "r"(a[2]), "r"(a[3]), "r"(b[0]), "r"(b[1]));
}

// ---------------- fp32 -> bf16 hi/lo split ----------------
__global__ __launch_bounds__(256) void split_kernel(
    const float4* __restrict__ in, uint2* __restrict__ hi, uint2* __restrict__ lo, int n4)
{
    int i = blockIdx.x * blockDim.x + threadIdx.x;
    if (i >= n4) return;
    float4 v = in[i];
    __nv_bfloat16 h0 = __float2bfloat16(v.x), h1 = __float2bfloat16(v.y);
    __nv_bfloat16 h2 = __float2bfloat16(v.z), h3 = __float2bfloat16(v.w);
    __nv_bfloat16 l0 = __float2bfloat16(v.x - __bfloat162float(h0));
    __nv_bfloat16 l1 = __float2bfloat16(v.y - __bfloat162float(h1));
    __nv_bfloat16 l2 = __float2bfloat16(v.z - __bfloat162float(h2));
    __nv_bfloat16 l3 = __float2bfloat16(v.w - __bfloat162float(h3));
    uint2 H, L;
    H.x = (uint32_t)__bfloat16_as_ushort(h0) | ((uint32_t)__bfloat16_as_ushort(h1) << 16);
    H.y = (uint32_t)__bfloat16_as_ushort(h2) | ((uint32_t)__bfloat16_as_ushort(h3) << 16);
    L.x = (uint32_t)__bfloat16_as_ushort(l0) | ((uint32_t)__bfloat16_as_ushort(l1) << 16);
    L.y = (uint32_t)__bfloat16_as_ushort(l2) | ((uint32_t)__bfloat16_as_ushort(l3) << 16);
    hi[i] = H; lo[i] = L;
}

// ---------------- mma.sync GEMM: C = A * W^T + bias (bf16 hi/lo 3-split) ----
// CTA 128x128, BK=32, 8 warps (4M x 2N), warp tile 32x64, 3-stage cp.async ring.
// Per-ks swizzled fragment bases (immediates elsewhere); ks1 A fragments
// prefetched during ks0's lo-pass.
__global__ __launch_bounds__(256, 2) void gemm_mma(
    const __nv_bfloat16* __restrict__ Ahi, const __nv_bfloat16* __restrict__ Alo,
    const __nv_bfloat16* __restrict__ Whi, const __nv_bfloat16* __restrict__ Wlo,
    const float* __restrict__ bias, float* __restrict__ C)
{
    extern __shared__ __align__(1024) char smem[];
    const uint32_t sbase = smem_u32(smem);

    const int tid = threadIdx.x;
    const int wid = tid >> 5;
    const int lane = tid & 31;
    const int wm = wid & 3;
    const int wn = wid >> 2;
    const int row0 = blockIdx.y * BM;
    const int col0 = blockIdx.x * BN;

    // loader constants (per thread): two (row, col8) slots
    const int r0 = tid >> 2, c0 = tid & 3;
    const uint32_t so0 = SWZ((uint32_t)(r0 * 64 + c0 * 16));
    const uint32_t so1 = SWZ((uint32_t)((r0 + 64) * 64 + c0 * 16));
    const size_t go0 = (size_t)r0 * KK + c0 * 8;
    const size_t go1 = (size_t)(r0 + 64) * KK + c0 * 8;

    const __nv_bfloat16* Ah = Ahi + (size_t)row0 * KK;
    const __nv_bfloat16* Al = Alo + (size_t)row0 * KK;
    const __nv_bfloat16* Wh = Whi + (size_t)col0 * KK;
    const __nv_bfloat16* Wl = Wlo + (size_t)col0 * KK;

    auto load_stage = [&](int kt, int s) {
        const uint32_t st = sbase + s * STAGE_B;
        const int kof = kt * BK;
        cp16(st + 0 * MAT_B + so0, Ah + go0 + kof);
        cp16(st + 0 * MAT_B + so1, Ah + go1 + kof);
        cp16(st + 1 * MAT_B + so0, Al + go0 + kof);
        cp16(st + 1 * MAT_B + so1, Al + go1 + kof);
        cp16(st + 2 * MAT_B + so0, Wh + go0 + kof);
        cp16(st + 2 * MAT_B + so1, Wh + go1 + kof);
        cp16(st + 3 * MAT_B + so0, Wl + go0 + kof);
        cp16(st + 3 * MAT_B + so1, Wl + go1 + kof);
        cp_commit();
    };

    float acc[2][8][4];
#pragma unroll
    for (int t = 0; t < 2; t++)
#pragma unroll
        for (int n = 0; n < 8; n++)
#pragma unroll
            for (int q = 0; q < 4; q++) acc[t][n][q] = 0.0f;

    // per-lane swizzled fragment bases, one per k-step (ks delta NOT linear)
    const int arow = ((lane >> 3) & 1) * 8 + (lane & 7);
    const int akof = (lane >> 4) * 16;
    const int brow = ((lane >> 4) & 1) * 8 + (lane & 7);
    const int bkof = ((lane >> 3) & 1) * 16;
    const uint32_t arawb = (uint32_t)((wm * 32 + arow) * 64 + akof);
    const uint32_t brawb = (uint32_t)((wn * 64 + brow) * 64 + bkof);
    uint32_t aswz[2], bswz[2];
    aswz[0] = SWZ(arawb);      aswz[1] = SWZ(arawb + 32);
    bswz[0] = SWZ(brawb);      bswz[1] = SWZ(brawb + 32);

    load_stage(0, 0);
    load_stage(1, 1);

    for (int kt = 0; kt < NKIT; kt++) {
        cp_wait<1>();
        __syncthreads();

        if (kt + 2 < NKIT) {
            int s = kt + 2; while (s >= NSTAGE) s -= NSTAGE;
            load_stage(kt + 2, s);
        }

        int cs = kt; while (cs >= NSTAGE) cs -= NSTAGE;
        const uint32_t stg = sbase + cs * STAGE_B;
        // per-ks operand bases
        const uint32_t aH0 = stg + aswz[0],            aH1 = stg + aswz[1];
        const uint32_t aL0 = aH0 + MAT_B,              aL1 = aH1 + MAT_B;
        const uint32_t bH0 = stg + 2 * MAT_B + bswz[0], bH1 = stg + 2 * MAT_B + bswz[1];
        const uint32_t bL0 = bH0 + MAT_B,              bL1 = bH1 + MAT_B;

        uint32_t ah[2][2][4], al[2][4], bf[2][4];

        // ks0 A fragments
        ldsm4(ah[0][0], aH0);
        ldsm4(ah[0][1], aH0 + 1024);
        ldsm4(al[0],    aL0);
        ldsm4(al[1],    aL0 + 1024);

#pragma unroll
        for (int ks = 0; ks < 2; ks++) {
            const uint32_t bH = ks ? bH1 : bH0;
            const uint32_t bL = ks ? bL1 : bL0;

            // hi pass: B pipeline; uses ah[ks] and al (al holds ks data)
            ldsm4(bf[0], bH);
#pragma unroll
            for (int p = 0; p < 4; p++) {
                if (p < 3) ldsm4(bf[(p + 1) & 1], bH + (p + 1) * 1024);
                else       ldsm4(bf[(p + 1) & 1], bL);
                const uint32_t* r4 = bf[p & 1];
#pragma unroll
                for (int t = 0; t < 2; t++) {
                    mma16816(acc[t][2 * p],     ah[ks][t], r4);
                    mma16816(acc[t][2 * p + 1], ah[ks][t], r4 + 2);
                    mma16816(acc[t][2 * p],     al[t], r4);
                    mma16816(acc[t][2 * p + 1], al[t], r4 + 2);
                }
            }
            // lo pass: uses only ah[ks]; al is dead -> prefetch ks1 A here
#pragma unroll
            for (int p = 0; p < 4; p++) {
                if (p < 3) ldsm4(bf[(p + 1) & 1], bL + (p + 1) * 1024);
                if (ks == 0) {
                    if (p == 0) ldsm4(al[0],    aL1);
                    if (p == 1) ldsm4(al[1],    aL1 + 1024);
                    if (p == 2) ldsm4(ah[1][0], aH1);
                    if (p == 3) ldsm4(ah[1][1], aH1 + 1024);
                }
                const uint32_t* r4 = bf[p & 1];
#pragma unroll
                for (int t = 0; t < 2; t++) {
                    mma16816(acc[t][2 * p],     ah[ks][t], r4);
                    mma16816(acc[t][2 * p + 1], ah[ks][t], r4 + 2);
                }
            }
        }
    }

    const int erow = row0 + wm * 32 + (lane >> 2);
    const int ecol0 = col0 + wn * 64 + 2 * (lane & 3);
#pragma unroll
    for (int t = 0; t < 2; t++) {
#pragma unroll
        for (int n = 0; n < 8; n++) {
            const int col = ecol0 + n * 8;
            const float2 bv = *(const float2*)(bias + col);
            float2 v0, v1;
            v0.x = acc[t][n][0] + bv.x; v0.y = acc[t][n][1] + bv.y;
            v1.x = acc[t][n][2] + bv.x; v1.y = acc[t][n][3] + bv.y;
            *(float2*)(C + (size_t)(erow + t * 16) * N2H + col) = v0;
            *(float2*)(C + (size_t)(erow + t * 16 + 8) * N2H + col) = v1;
        }
    }
}

// ---------------- scan ----------------
__device__ __forceinline__ void gate_cd(float gate, float hid, float& c, float& d) {
    const float t = __expf(-gate);
    const float inv = __fdividef(1.0f, 1.0f + t);
    c = t * inv;                  // 1 - sigmoid(gate)
    const float gx = (hid >= 0.0f) ? (hid + 0.5f)
                                   : __fdividef(1.0f, 1.0f + __expf(-hid));
    d = inv * gx;                 // sigmoid(gate) * g(hid)
}

// pass 1: per (channel, chunk): C = prod c, V = value with h_in = 0
__global__ __launch_bounds__(128) void scan1_kernel(
    const float* __restrict__ gh, float* __restrict__ Co, float* __restrict__ Vo)
{
    const int idx = blockIdx.x * blockDim.x + threadIdx.x;
    const int hh = idx & (HH - 1);
    const int rest = idx >> 10;
    const int chunk = rest & (NC - 1);
    const int b = rest >> 5;

    const float* g = gh + (size_t)(b * SS + chunk * CS) * N2H + hh;
    float Ca = 1.0f, Va = 0.0f;
#pragma unroll 4
    for (int s = 0; s < CS; s++) {
        float c, d;
        gate_cd(g[(size_t)s * N2H], g[(size_t)s * N2H + HH], c, d);
        Ca *= c;
        Va = c * Va + d;
    }
    const int ch = b * HH + hh;
    Co[chunk * NCH + ch] = Ca;
    Vo[chunk * NCH + ch] = Va;
}

// pass 2: per channel: scan over chunks, emit per-chunk h_in + finals
__global__ __launch_bounds__(128) void scan2_kernel(
    const float* __restrict__ Co, const float* __restrict__ Vo,
    const float* __restrict__ hprev, float* __restrict__ hin,
    float* __restrict__ finals)
{
    const int ch = blockIdx.x * blockDim.x + threadIdx.x;
    const float hp = hprev[ch];
    float h = (hp >= 0.0f) ? (hp + 0.5f) : __fdividef(1.0f, 1.0f + __expf(-hp));
#pragma unroll
    for (int k = 0; k < NC; k++) {
        hin[k * NCH + ch] = h;
        h = Co[k * NCH + ch] * h + Vo[k * NCH + ch];
    }
    finals[ch] = h;
}

// pass 3: recompute with correct h_in; input read as bf16 hi/lo pair (x = hi+lo);
// residual add; write either next-layer hi/lo split IN PLACE, or final fp32 out.
__global__ __launch_bounds__(128) void scan3_kernel(
    const float* __restrict__ gh,
    __nv_bfloat16* __restrict__ ihi, __nv_bfloat16* __restrict__ ilo,
    const float* __restrict__ hin, float* __restrict__ outF)
{
    const int idx = blockIdx.x * blockDim.x + threadIdx.x;
    const int hh = idx & (HH - 1);
    const int rest = idx >> 10;
    const int chunk = rest & (NC - 1);
    const int b = rest >> 5;
    const int ch = b * HH + hh;

    const size_t base2h = (size_t)(b * SS + chunk * CS) * N2H + hh;
    const size_t base1h = (size_t)(b * SS + chunk * CS) * HH + hh;
    const float* g = gh + base2h;

    float h = hin[chunk * NCH + ch];
#pragma unroll 4
    for (int s = 0; s < CS; s++) {
        float c, d;
        gate_cd(g[(size_t)s * N2H], g[(size_t)s * N2H + HH], c, d);
        h = c * h + d;
        const size_t p = base1h + (size_t)s * HH;
        const float xin = __bfloat162float(ihi[p]) + __bfloat162float(ilo[p]);
        const float o = h + xin;
        if (outF) {
            outF[p] = o;
        } else {
            const __nv_bfloat16 hb = __float2bfloat16(o);
            ihi[p] = hb;
            ilo[p] = __float2bfloat16(o - __bfloat162float(hb));
        }
    }
}

// ---------------- launch ----------------
extern "C" void kernel_launch(void* const* d_in, const int* in_sizes, int n_in,
                              void* d_out, int out_size)
{
    const float* x  = (const float*)d_in[0];  // (B,S,D)
    const float* h0 = (const float*)d_in[1];  // (L,B,1,H)
    const float* W0 = (const float*)d_in[2];  // (2H,D)
    const float* b0 = (const float*)d_in[3];  // (2H,)
    const float* Wl = (const float*)d_in[4];  // (L-1,2H,H)
    const float* bl = (const float*)d_in[5];  // (L-1,2H)

    float* out    = (float*)d_out;
    float* finals = out + (size_t)MM * HH;

    float *gh, *Cb, *Vb, *hinb;
    __nv_bfloat16 *ahi, *alo, *whi, *wlo;
    cudaGetSymbolAddress((void**)&gh,   g_gh);
    cudaGetSymbolAddress((void**)&ahi,  g_ahi);
    cudaGetSymbolAddress((void**)&alo,  g_alo);
    cudaGetSymbolAddress((void**)&whi,  g_whi);
    cudaGetSymbolAddress((void**)&wlo,  g_wlo);
    cudaGetSymbolAddress((void**)&Cb,   g_C);
    cudaGetSymbolAddress((void**)&Vb,   g_V);
    cudaGetSymbolAddress((void**)&hinb, g_hin);

    cudaFuncSetAttribute(gemm_mma, cudaFuncAttributeMaxDynamicSharedMemorySize, SMEM_TOTAL);

    // layer-0 input + all weights -> bf16 hi/lo
    {
        int n4 = (MM * KK) / 4;
        split_kernel<<<(n4 + 255) / 256, 256>>>((const float4*)x, (uint2*)ahi, (uint2*)alo, n4);
        n4 = (N2H * KK) / 4;
        split_kernel<<<(n4 + 255) / 256, 256>>>((const float4*)W0, (uint2*)whi, (uint2*)wlo, n4);
        n4 = (3 * N2H * KK) / 4;
        split_kernel<<<(n4 + 255) / 256, 256>>>((const float4*)Wl,
                                                (uint2*)(whi + (size_t)N2H * KK),
                                                (uint2*)(wlo + (size_t)N2H * KK), n4);
    }

    const dim3 ggrid(N2H / BN, MM / BM);           // (16, 128)
    const int scan13_blocks = (NCH * NC) / 128;    // 2048
    const int scan2_blocks = NCH / 128;            // 64

    for (int l = 0; l < LL; l++) {
        const __nv_bfloat16* Whl = whi + (size_t)l * N2H * KK;
        const __nv_bfloat16* Wll = wlo + (size_t)l * N2H * KK;
        const float* bb = (l == 0) ? b0 : (bl + (size_t)(l - 1) * N2H);

        gemm_mma<<<ggrid, 256, SMEM_TOTAL>>>(ahi, alo, Whl, Wll, bb, gh);

        scan1_kernel<<<scan13_blocks, 128>>>(gh, Cb, Vb);
        scan2_kernel<<<scan2_blocks, 128>>>(Cb, Vb, h0 + (size_t)l * NCH, hinb,
                                            finals + (size_t)l * NCH);
        scan3_kernel<<<scan13_blocks, 128>>>(gh, ahi, alo, hinb,
                                             (l == LL - 1) ? out : nullptr);
    }
}

// round 9
// speedup vs baseline: 4.3418x; 1.3448x over previous
#include <cuda_runtime.h>
#include <cuda_bf16.h>
#include <cuda_fp16.h>
#include <cstdint>

// ---------------- problem dims ----------------
#define BB 8
#define SS 2048
#define HH 1024
#define LL 4
#define MM (BB * SS)       // 16384
#define N2H (2 * HH)       // 2048
#define KK 1024

// scan chunking
#define NC 32
#define CS (SS / NC)       // 64
#define NCH (BB * HH)      // 8192

// GEMM tiling
#define BM 128
#define BN 128
#define BK 32
#define NKIT (KK / BK)     // 32

#define MAT_B (BM * 64)                 // 8192 bytes per matrix tile (64B rows)
#define STAGE_B (3 * MAT_B)             // A, Whi, Wlo = 24576
#define NSTAGE 4
#define SMEM_TOTAL (NSTAGE * STAGE_B)   // 98304 -> 2 CTAs/SM

// SW64-style swizzle: XOR bits[5:4] with bits[8:7]. Deltas at bit>=10 commute;
// the +32 k-step does NOT -> per-ks precomputed swizzled bases.
#define SWZ(off) ((off) ^ (((off) >> 3) & 0x30))

#define WSCALE 64.0f
#define WINV   0.015625f

// ---------------- scratch (device globals; allocation banned) ----------------
__device__ float   g_gh  [(size_t)MM * N2H];
__device__ float   g_act [(size_t)MM * HH];     // fp32 residual stream
__device__ __half  g_af16[(size_t)MM * KK];     // fp16 GEMM copy of activations
__device__ __half  g_whi [(size_t)LL * N2H * KK];
__device__ __half  g_wlo [(size_t)LL * N2H * KK];
__device__ float   g_C   [(size_t)NC * NCH];
__device__ float   g_V   [(size_t)NC * NCH];
__device__ float   g_hin [(size_t)NC * NCH];

// ---------------- PTX helpers ----------------
__device__ __forceinline__ uint32_t smem_u32(const void* p) {
    uint32_t a;
    asm("{ .reg .u64 t; cvta.to.shared.u64 t, %1; cvt.u32.u64 %0, t; }"
        : "=r"(a) : "l"(p));
    return a;
}
__device__ __forceinline__ void cp16(uint32_t s, const void* g) {
    asm volatile("cp.async.cg.shared.global [%0], [%1], 16;" :: "r"(s), "l"(g));
}
__device__ __forceinline__ void cp_commit() {
    asm volatile("cp.async.commit_group;" ::: "memory");
}
template <int N>
__device__ __forceinline__ void cp_wait() {
    asm volatile("cp.async.wait_group %0;" :: "n"(N) : "memory");
}
__device__ __forceinline__ void ldsm4(uint32_t* r, uint32_t addr) {
    asm volatile("ldmatrix.sync.aligned.m8n8.x4.shared.b16 {%0,%1,%2,%3}, [%4];"
                 : "=r"(r[0]), "=r"(r[1]), "=r"(r[2]), "=r"(r[3]) : "r"(addr));
}
__device__ __forceinline__ void mma16816(float* c, const uint32_t* a, const uint32_t* b) {
    asm volatile(
        "mma.sync.aligned.m16n8k16.row.col.f32.f16.f16.f32 "
        "{%0,%1,%2,%3}, {%4,%5,%6,%7}, {%8,%9}, {%0,%1,%2,%3};"
        : "+f"(c[0]), "+f"(c[1]), "+f"(c[2]), "+f"(c[3])
        : "r"(a[0]), "r"(a[1]), "r"(a[2]), "r"(a[3]), "r"(b[0]), "r"(b[1]));
}

// ---------------- converts ----------------
// fp32 -> fp16 (activations)
__global__ __launch_bounds__(256) void tof16_kernel(
    const float4* __restrict__ in, uint2* __restrict__ o16, int n4)
{
    int i = blockIdx.x * blockDim.x + threadIdx.x;
    if (i >= n4) return;
    float4 v = in[i];
    uint2 H;
    H.x = (uint32_t)__half_as_ushort(__float2half(v.x))
        | ((uint32_t)__half_as_ushort(__float2half(v.y)) << 16);
    H.y = (uint32_t)__half_as_ushort(__float2half(v.z))
        | ((uint32_t)__half_as_ushort(__float2half(v.w)) << 16);
    o16[i] = H;
}

// fp32 weights -> fp16 hi/lo of (64*W)
__global__ __launch_bounds__(256) void splitw_kernel(
    const float4* __restrict__ in, uint2* __restrict__ hi, uint2* __restrict__ lo, int n4)
{
    int i = blockIdx.x * blockDim.x + threadIdx.x;
    if (i >= n4) return;
    float4 v = in[i];
    float s0 = v.x * WSCALE, s1 = v.y * WSCALE, s2 = v.z * WSCALE, s3 = v.w * WSCALE;
    __half h0 = __float2half(s0), h1 = __float2half(s1);
    __half h2 = __float2half(s2), h3 = __float2half(s3);
    __half l0 = __float2half(s0 - __half2float(h0));
    __half l1 = __float2half(s1 - __half2float(h1));
    __half l2 = __float2half(s2 - __half2float(h2));
    __half l3 = __float2half(s3 - __half2float(h3));
    uint2 H, L;
    H.x = (uint32_t)__half_as_ushort(h0) | ((uint32_t)__half_as_ushort(h1) << 16);
    H.y = (uint32_t)__half_as_ushort(h2) | ((uint32_t)__half_as_ushort(h3) << 16);
    L.x = (uint32_t)__half_as_ushort(l0) | ((uint32_t)__half_as_ushort(l1) << 16);
    L.y = (uint32_t)__half_as_ushort(l2) | ((uint32_t)__half_as_ushort(l3) << 16);
    hi[i] = H; lo[i] = L;
}

// ---------------- mma.sync GEMM: C = (A * (64W)^T)/64 + bias ----------------
// A fp16 (M,K); W fp16 hi/lo (N,K) pre-scaled by 64; C (M,N2H) fp32.
// CTA 128x128, BK=32, 8 warps (4M x 2N), warp tile 32x64.
// 4-stage cp.async ring (prefetch depth 3), 2 MMA passes per k16.
__global__ __launch_bounds__(256, 2) void gemm_mma(
    const __half* __restrict__ Af, const __half* __restrict__ Whi,
    const __half* __restrict__ Wlo, const float* __restrict__ bias,
    float* __restrict__ C)
{
    extern __shared__ __align__(1024) char smem[];
    const uint32_t sbase = smem_u32(smem);

    const int tid = threadIdx.x;
    const int wid = tid >> 5;
    const int lane = tid & 31;
    const int wm = wid & 3;
    const int wn = wid >> 2;
    const int row0 = blockIdx.y * BM;
    const int col0 = blockIdx.x * BN;

    const int r0 = tid >> 2, c0 = tid & 3;
    const uint32_t so0 = SWZ((uint32_t)(r0 * 64 + c0 * 16));
    const uint32_t so1 = SWZ((uint32_t)((r0 + 64) * 64 + c0 * 16));
    const size_t go0 = (size_t)r0 * KK + c0 * 8;
    const size_t go1 = (size_t)(r0 + 64) * KK + c0 * 8;

    const __half* Ap = Af  + (size_t)row0 * KK;
    const __half* Wh = Whi + (size_t)col0 * KK;
    const __half* Wl = Wlo + (size_t)col0 * KK;

    auto load_stage = [&](int kt, int s) {
        const uint32_t st = sbase + s * STAGE_B;
        const int kof = kt * BK;
        cp16(st + 0 * MAT_B + so0, Ap + go0 + kof);
        cp16(st + 0 * MAT_B + so1, Ap + go1 + kof);
        cp16(st + 1 * MAT_B + so0, Wh + go0 + kof);
        cp16(st + 1 * MAT_B + so1, Wh + go1 + kof);
        cp16(st + 2 * MAT_B + so0, Wl + go0 + kof);
        cp16(st + 2 * MAT_B + so1, Wl + go1 + kof);
        cp_commit();
    };

    float acc[2][8][4];
#pragma unroll
    for (int t = 0; t < 2; t++)
#pragma unroll
        for (int n = 0; n < 8; n++)
#pragma unroll
            for (int q = 0; q < 4; q++) acc[t][n][q] = 0.0f;

    const int arow = ((lane >> 3) & 1) * 8 + (lane & 7);
    const int akof = (lane >> 4) * 16;
    const int brow = ((lane >> 4) & 1) * 8 + (lane & 7);
    const int bkof = ((lane >> 3) & 1) * 16;
    const uint32_t arawb = (uint32_t)((wm * 32 + arow) * 64 + akof);
    const uint32_t brawb = (uint32_t)((wn * 64 + brow) * 64 + bkof);
    uint32_t aswz[2], bswz[2];
    aswz[0] = SWZ(arawb);  aswz[1] = SWZ(arawb + 32);
    bswz[0] = SWZ(brawb);  bswz[1] = SWZ(brawb + 32);

    load_stage(0, 0);
    load_stage(1, 1);
    load_stage(2, 2);

    for (int kt = 0; kt < NKIT; kt++) {
        cp_wait<2>();
        __syncthreads();

        if (kt + 3 < NKIT) load_stage(kt + 3, (kt + 3) & 3);

        const uint32_t stg = sbase + (kt & 3) * STAGE_B;
        const uint32_t aH0 = stg + aswz[0],             aH1 = stg + aswz[1];
        const uint32_t wH0 = stg + MAT_B + bswz[0],     wH1 = stg + MAT_B + bswz[1];
        const uint32_t wL0 = wH0 + MAT_B,               wL1 = wH1 + MAT_B;

        uint32_t ah[2][2][4], bf[2][4];

        ldsm4(ah[0][0], aH0);
        ldsm4(ah[0][1], aH0 + 1024);

#pragma unroll
        for (int ks = 0; ks < 2; ks++) {
            const uint32_t bH = ks ? wH1 : wH0;
            const uint32_t bL = ks ? wL1 : wL0;

            // W_hi pass
            ldsm4(bf[0], bH);
#pragma unroll
            for (int p = 0; p < 4; p++) {
                if (p < 3) ldsm4(bf[(p + 1) & 1], bH + (p + 1) * 1024);
                else       ldsm4(bf[(p + 1) & 1], bL);
                const uint32_t* r4 = bf[p & 1];
#pragma unroll
                for (int t = 0; t < 2; t++) {
                    mma16816(acc[t][2 * p],     ah[ks][t], r4);
                    mma16816(acc[t][2 * p + 1], ah[ks][t], r4 + 2);
                }
            }
            // W_lo pass; prefetch ks1 A fragments here
#pragma unroll
            for (int p = 0; p < 4; p++) {
                if (p < 3) ldsm4(bf[(p + 1) & 1], bL + (p + 1) * 1024);
                if (ks == 0) {
                    if (p == 0) ldsm4(ah[1][0], aH1);
                    if (p == 1) ldsm4(ah[1][1], aH1 + 1024);
                }
                const uint32_t* r4 = bf[p & 1];
#pragma unroll
                for (int t = 0; t < 2; t++) {
                    mma16816(acc[t][2 * p],     ah[ks][t], r4);
                    mma16816(acc[t][2 * p + 1], ah[ks][t], r4 + 2);
                }
            }
        }
    }

    const int erow = row0 + wm * 32 + (lane >> 2);
    const int ecol0 = col0 + wn * 64 + 2 * (lane & 3);
#pragma unroll
    for (int t = 0; t < 2; t++) {
#pragma unroll
        for (int n = 0; n < 8; n++) {
            const int col = ecol0 + n * 8;
            const float2 bv = *(const float2*)(bias + col);
            float2 v0, v1;
            v0.x = fmaf(acc[t][n][0], WINV, bv.x); v0.y = fmaf(acc[t][n][1], WINV, bv.y);
            v1.x = fmaf(acc[t][n][2], WINV, bv.x); v1.y = fmaf(acc[t][n][3], WINV, bv.y);
            *(float2*)(C + (size_t)(erow + t * 16) * N2H + col) = v0;
            *(float2*)(C + (size_t)(erow + t * 16 + 8) * N2H + col) = v1;
        }
    }
}

// ---------------- scan ----------------
__device__ __forceinline__ void gate_cd(float gate, float hid, float& c, float& d) {
    const float t = __expf(-gate);
    const float inv = __fdividef(1.0f, 1.0f + t);
    c = t * inv;                  // 1 - sigmoid(gate)
    const float gx = (hid >= 0.0f) ? (hid + 0.5f)
                                   : __fdividef(1.0f, 1.0f + __expf(-hid));
    d = inv * gx;                 // sigmoid(gate) * g(hid)
}

__global__ __launch_bounds__(128) void scan1_kernel(
    const float* __restrict__ gh, float* __restrict__ Co, float* __restrict__ Vo)
{
    const int idx = blockIdx.x * blockDim.x + threadIdx.x;
    const int hh = idx & (HH - 1);
    const int rest = idx >> 10;
    const int chunk = rest & (NC - 1);
    const int b = rest >> 5;

    const float* g = gh + (size_t)(b * SS + chunk * CS) * N2H + hh;
    float Ca = 1.0f, Va = 0.0f;
#pragma unroll 4
    for (int s = 0; s < CS; s++) {
        float c, d;
        gate_cd(g[(size_t)s * N2H], g[(size_t)s * N2H + HH], c, d);
        Ca *= c;
        Va = c * Va + d;
    }
    const int ch = b * HH + hh;
    Co[chunk * NCH + ch] = Ca;
    Vo[chunk * NCH + ch] = Va;
}

__global__ __launch_bounds__(128) void scan2_kernel(
    const float* __restrict__ Co, const float* __restrict__ Vo,
    const float* __restrict__ hprev, float* __restrict__ hin,
    float* __restrict__ finals)
{
    const int ch = blockIdx.x * blockDim.x + threadIdx.x;
    const float hp = hprev[ch];
    float h = (hp >= 0.0f) ? (hp + 0.5f) : __fdividef(1.0f, 1.0f + __expf(-hp));
#pragma unroll
    for (int k = 0; k < NC; k++) {
        hin[k * NCH + ch] = h;
        h = Co[k * NCH + ch] * h + Vo[k * NCH + ch];
    }
    finals[ch] = h;
}

// pass 3: recompute with h_in; fp32 residual add (in-place capable);
// optionally emit fp16 copy for the next layer's GEMM.
__global__ __launch_bounds__(128) void scan3_kernel(
    const float* __restrict__ gh, const float* __restrict__ inp,
    const float* __restrict__ hin, float* __restrict__ outF,
    __half* __restrict__ o16)
{
    const int idx = blockIdx.x * blockDim.x + threadIdx.x;
    const int hh = idx & (HH - 1);
    const int rest = idx >> 10;
    const int chunk = rest & (NC - 1);
    const int b = rest >> 5;
    const int ch = b * HH + hh;

    const size_t base2h = (size_t)(b * SS + chunk * CS) * N2H + hh;
    const size_t base1h = (size_t)(b * SS + chunk * CS) * HH + hh;
    const float* g = gh + base2h;

    float h = hin[chunk * NCH + ch];
#pragma unroll 4
    for (int s = 0; s < CS; s++) {
        float c, d;
        gate_cd(g[(size_t)s * N2H], g[(size_t)s * N2H + HH], c, d);
        h = c * h + d;
        const size_t p = base1h + (size_t)s * HH;
        const float o = h + inp[p];
        outF[p] = o;
        if (o16) o16[p] = __float2half(o);
    }
}

// ---------------- launch ----------------
extern "C" void kernel_launch(void* const* d_in, const int* in_sizes, int n_in,
                              void* d_out, int out_size)
{
    const float* x  = (const float*)d_in[0];  // (B,S,D)
    const float* h0 = (const float*)d_in[1];  // (L,B,1,H)
    const float* W0 = (const float*)d_in[2];  // (2H,D)
    const float* b0 = (const float*)d_in[3];  // (2H,)
    const float* Wl = (const float*)d_in[4];  // (L-1,2H,H)
    const float* bl = (const float*)d_in[5];  // (L-1,2H)

    float* out    = (float*)d_out;
    float* finals = out + (size_t)MM * HH;

    float *gh, *act, *Cb, *Vb, *hinb;
    __half *af16, *whi, *wlo;
    cudaGetSymbolAddress((void**)&gh,   g_gh);
    cudaGetSymbolAddress((void**)&act,  g_act);
    cudaGetSymbolAddress((void**)&af16, g_af16);
    cudaGetSymbolAddress((void**)&whi,  g_whi);
    cudaGetSymbolAddress((void**)&wlo,  g_wlo);
    cudaGetSymbolAddress((void**)&Cb,   g_C);
    cudaGetSymbolAddress((void**)&Vb,   g_V);
    cudaGetSymbolAddress((void**)&hinb, g_hin);

    cudaFuncSetAttribute(gemm_mma, cudaFuncAttributeMaxDynamicSharedMemorySize, SMEM_TOTAL);

    // x -> fp16; weights -> fp16 hi/lo of 64*W
    {
        int n4 = (MM * KK) / 4;
        tof16_kernel<<<(n4 + 255) / 256, 256>>>((const float4*)x, (uint2*)af16, n4);
        n4 = (N2H * KK) / 4;
        splitw_kernel<<<(n4 + 255) / 256, 256>>>((const float4*)W0, (uint2*)whi, (uint2*)wlo, n4);
        n4 = (3 * N2H * KK) / 4;
        splitw_kernel<<<(n4 + 255) / 256, 256>>>((const float4*)Wl,
                                                 (uint2*)(whi + (size_t)N2H * KK),
                                                 (uint2*)(wlo + (size_t)N2H * KK), n4);
    }

    const dim3 ggrid(N2H / BN, MM / BM);           // (16, 128)
    const int scan13_blocks = (NCH * NC) / 128;    // 2048
    const int scan2_blocks = NCH / 128;            // 64

    for (int l = 0; l < LL; l++) {
        const __half* Whl = whi + (size_t)l * N2H * KK;
        const __half* Wll = wlo + (size_t)l * N2H * KK;
        const float* bb = (l == 0) ? b0 : (bl + (size_t)(l - 1) * N2H);

        gemm_mma<<<ggrid, 256, SMEM_TOTAL>>>(af16, Whl, Wll, bb, gh);

        scan1_kernel<<<scan13_blocks, 128>>>(gh, Cb, Vb);
        scan2_kernel<<<scan2_blocks, 128>>>(Cb, Vb, h0 + (size_t)l * NCH, hinb,
                                            finals + (size_t)l * NCH);

        const float* inp = (l == 0) ? x : act;
        float* o = (l == LL - 1) ? out : act;
        scan3_kernel<<<scan13_blocks, 128>>>(gh, inp, hinb, o,
                                             (l == LL - 1) ? nullptr : af16);
    }
}

// round 10
// speedup vs baseline: 6.6324x; 1.5276x over previous
#include <cuda_runtime.h>
#include <cuda_bf16.h>
#include <cuda_fp16.h>
#include <cstdint>

// ---------------- problem dims ----------------
#define BB 8
#define SS 2048
#define HH 1024
#define LL 4
#define MM (BB * SS)       // 16384
#define N2H (2 * HH)       // 2048
#define KK 1024

// scan chunking
#define NC 32
#define CS (SS / NC)       // 64
#define NCH (BB * HH)      // 8192

// GEMM tiling
#define BM 128
#define BN 128
#define BK 32
#define NKIT (KK / BK)     // 32

#define MAT_B (BM * 64)                 // 8192 bytes per matrix tile (64B rows)
#define STAGE_B (2 * MAT_B)             // A, W = 16384
#define NSTAGE 4
#define SMEM_TOTAL (NSTAGE * STAGE_B)   // 65536 -> 2 CTAs/SM easily

// SW64-style swizzle: XOR bits[5:4] with bits[8:7]. Deltas at bit>=10 commute;
// the +32 k-step does NOT -> per-ks precomputed swizzled bases.
#define SWZ(off) ((off) ^ (((off) >> 3) & 0x30))

#define WSCALE 64.0f
#define WINV   0.015625f

// ---------------- scratch (device globals; allocation banned) ----------------
__device__ float   g_gh  [(size_t)MM * N2H];
__device__ float   g_act [(size_t)MM * HH];     // fp32 residual stream
__device__ __half  g_af16[(size_t)MM * KK];     // fp16 GEMM copy of activations
__device__ __half  g_w16 [(size_t)LL * N2H * KK];
__device__ float   g_C   [(size_t)NC * NCH];
__device__ float   g_V   [(size_t)NC * NCH];
__device__ float   g_hin [(size_t)NC * NCH];

// ---------------- PTX helpers ----------------
__device__ __forceinline__ uint32_t smem_u32(const void* p) {
    uint32_t a;
    asm("{ .reg .u64 t; cvta.to.shared.u64 t, %1; cvt.u32.u64 %0, t; }"
        : "=r"(a) : "l"(p));
    return a;
}
__device__ __forceinline__ void cp16(uint32_t s, const void* g) {
    asm volatile("cp.async.cg.shared.global [%0], [%1], 16;" :: "r"(s), "l"(g));
}
__device__ __forceinline__ void cp_commit() {
    asm volatile("cp.async.commit_group;" ::: "memory");
}
template <int N>
__device__ __forceinline__ void cp_wait() {
    asm volatile("cp.async.wait_group %0;" :: "n"(N) : "memory");
}
__device__ __forceinline__ void ldsm4(uint32_t* r, uint32_t addr) {
    asm volatile("ldmatrix.sync.aligned.m8n8.x4.shared.b16 {%0,%1,%2,%3}, [%4];"
                 : "=r"(r[0]), "=r"(r[1]), "=r"(r[2]), "=r"(r[3]) : "r"(addr));
}
__device__ __forceinline__ void mma16816(float* c, const uint32_t* a, const uint32_t* b) {
    asm volatile(
        "mma.sync.aligned.m16n8k16.row.col.f32.f16.f16.f32 "
        "{%0,%1,%2,%3}, {%4,%5,%6,%7}, {%8,%9}, {%0,%1,%2,%3};"
        : "+f"(c[0]), "+f"(c[1]), "+f"(c[2]), "+f"(c[3])
        : "r"(a[0]), "r"(a[1]), "r"(a[2]), "r"(a[3]), "r"(b[0]), "r"(b[1]));
}

// ---------------- converts ----------------
// fp32 -> fp16, optional pre-scale
__global__ __launch_bounds__(256) void tof16_kernel(
    const float4* __restrict__ in, uint2* __restrict__ o16, float scale, int n4)
{
    int i = blockIdx.x * blockDim.x + threadIdx.x;
    if (i >= n4) return;
    float4 v = in[i];
    uint2 H;
    H.x = (uint32_t)__half_as_ushort(__float2half(v.x * scale))
        | ((uint32_t)__half_as_ushort(__float2half(v.y * scale)) << 16);
    H.y = (uint32_t)__half_as_ushort(__float2half(v.z * scale))
        | ((uint32_t)__half_as_ushort(__float2half(v.w * scale)) << 16);
    o16[i] = H;
}

// ---------------- mma.sync GEMM: C = (A * (64W)^T)/64 + bias ----------------
// A fp16 (M,K); W fp16 (N,K) pre-scaled by 64; C (M,N2H) fp32.
// CTA 128x128, BK=32, 8 warps (4M x 2N), warp tile 32x64.
// 4-stage cp.async ring (prefetch depth 3), SINGLE fp16 pass per k16.
__global__ __launch_bounds__(256, 2) void gemm_mma(
    const __half* __restrict__ Af, const __half* __restrict__ Wf,
    const float* __restrict__ bias, float* __restrict__ C)
{
    extern __shared__ __align__(1024) char smem[];
    const uint32_t sbase = smem_u32(smem);

    const int tid = threadIdx.x;
    const int wid = tid >> 5;
    const int lane = tid & 31;
    const int wm = wid & 3;
    const int wn = wid >> 2;
    const int row0 = blockIdx.y * BM;
    const int col0 = blockIdx.x * BN;

    const int r0 = tid >> 2, c0 = tid & 3;
    const uint32_t so0 = SWZ((uint32_t)(r0 * 64 + c0 * 16));
    const uint32_t so1 = SWZ((uint32_t)((r0 + 64) * 64 + c0 * 16));
    const size_t go0 = (size_t)r0 * KK + c0 * 8;
    const size_t go1 = (size_t)(r0 + 64) * KK + c0 * 8;

    const __half* Ap = Af + (size_t)row0 * KK;
    const __half* Wp = Wf + (size_t)col0 * KK;

    auto load_stage = [&](int kt, int s) {
        const uint32_t st = sbase + s * STAGE_B;
        const int kof = kt * BK;
        cp16(st + 0 * MAT_B + so0, Ap + go0 + kof);
        cp16(st + 0 * MAT_B + so1, Ap + go1 + kof);
        cp16(st + 1 * MAT_B + so0, Wp + go0 + kof);
        cp16(st + 1 * MAT_B + so1, Wp + go1 + kof);
        cp_commit();
    };

    float acc[2][8][4];
#pragma unroll
    for (int t = 0; t < 2; t++)
#pragma unroll
        for (int n = 0; n < 8; n++)
#pragma unroll
            for (int q = 0; q < 4; q++) acc[t][n][q] = 0.0f;

    const int arow = ((lane >> 3) & 1) * 8 + (lane & 7);
    const int akof = (lane >> 4) * 16;
    const int brow = ((lane >> 4) & 1) * 8 + (lane & 7);
    const int bkof = ((lane >> 3) & 1) * 16;
    const uint32_t arawb = (uint32_t)((wm * 32 + arow) * 64 + akof);
    const uint32_t brawb = (uint32_t)((wn * 64 + brow) * 64 + bkof);
    uint32_t aswz[2], bswz[2];
    aswz[0] = SWZ(arawb);  aswz[1] = SWZ(arawb + 32);
    bswz[0] = SWZ(brawb);  bswz[1] = SWZ(brawb + 32);

    load_stage(0, 0);
    load_stage(1, 1);
    load_stage(2, 2);

    for (int kt = 0; kt < NKIT; kt++) {
        cp_wait<2>();
        __syncthreads();

        if (kt + 3 < NKIT) load_stage(kt + 3, (kt + 3) & 3);

        const uint32_t stg = sbase + (kt & 3) * STAGE_B;
        const uint32_t aH0 = stg + aswz[0],           aH1 = stg + aswz[1];
        const uint32_t wH0 = stg + MAT_B + bswz[0],   wH1 = stg + MAT_B + bswz[1];

        uint32_t ah[2][2][4], bf[2][4];

        ldsm4(ah[0][0], aH0);
        ldsm4(ah[0][1], aH0 + 1024);
        ldsm4(bf[0], wH0);

#pragma unroll
        for (int ks = 0; ks < 2; ks++) {
            const uint32_t bH = ks ? wH1 : wH0;
#pragma unroll
            for (int p = 0; p < 4; p++) {
                // prefetch next B fragment (crossing into ks1 at the seam)
                if (p < 3)        ldsm4(bf[(p + 1) & 1], bH + (p + 1) * 1024);
                else if (ks == 0) ldsm4(bf[(p + 1) & 1], wH1);
                // prefetch ks1 A fragments early in ks0
                if (ks == 0 && p == 0) ldsm4(ah[1][0], aH1);
                if (ks == 0 && p == 1) ldsm4(ah[1][1], aH1 + 1024);
                const uint32_t* r4 = bf[p & 1];
#pragma unroll
                for (int t = 0; t < 2; t++) {
                    mma16816(acc[t][2 * p],     ah[ks][t], r4);
                    mma16816(acc[t][2 * p + 1], ah[ks][t], r4 + 2);
                }
            }
        }
    }

    const int erow = row0 + wm * 32 + (lane >> 2);
    const int ecol0 = col0 + wn * 64 + 2 * (lane & 3);
#pragma unroll
    for (int t = 0; t < 2; t++) {
#pragma unroll
        for (int n = 0; n < 8; n++) {
            const int col = ecol0 + n * 8;
            const float2 bv = *(const float2*)(bias + col);
            float2 v0, v1;
            v0.x = fmaf(acc[t][n][0], WINV, bv.x); v0.y = fmaf(acc[t][n][1], WINV, bv.y);
            v1.x = fmaf(acc[t][n][2], WINV, bv.x); v1.y = fmaf(acc[t][n][3], WINV, bv.y);
            *(float2*)(C + (size_t)(erow + t * 16) * N2H + col) = v0;
            *(float2*)(C + (size_t)(erow + t * 16 + 8) * N2H + col) = v1;
        }
    }
}

// ---------------- scan ----------------
__device__ __forceinline__ void gate_cd(float gate, float hid, float& c, float& d) {
    const float t = __expf(-gate);
    const float inv = __fdividef(1.0f, 1.0f + t);
    c = t * inv;                  // 1 - sigmoid(gate)
    const float gx = (hid >= 0.0f) ? (hid + 0.5f)
                                   : __fdividef(1.0f, 1.0f + __expf(-hid));
    d = inv * gx;                 // sigmoid(gate) * g(hid)
}

__global__ __launch_bounds__(128) void scan1_kernel(
    const float* __restrict__ gh, float* __restrict__ Co, float* __restrict__ Vo)
{
    const int idx = blockIdx.x * blockDim.x + threadIdx.x;
    const int hh = idx & (HH - 1);
    const int rest = idx >> 10;
    const int chunk = rest & (NC - 1);
    const int b = rest >> 5;

    const float* g = gh + (size_t)(b * SS + chunk * CS) * N2H + hh;
    float Ca = 1.0f, Va = 0.0f;
#pragma unroll 4
    for (int s = 0; s < CS; s++) {
        float c, d;
        gate_cd(g[(size_t)s * N2H], g[(size_t)s * N2H + HH], c, d);
        Ca *= c;
        Va = c * Va + d;
    }
    const int ch = b * HH + hh;
    Co[chunk * NCH + ch] = Ca;
    Vo[chunk * NCH + ch] = Va;
}

__global__ __launch_bounds__(128) void scan2_kernel(
    const float* __restrict__ Co, const float* __restrict__ Vo,
    const float* __restrict__ hprev, float* __restrict__ hin,
    float* __restrict__ finals)
{
    const int ch = blockIdx.x * blockDim.x + threadIdx.x;
    const float hp = hprev[ch];
    float h = (hp >= 0.0f) ? (hp + 0.5f) : __fdividef(1.0f, 1.0f + __expf(-hp));
#pragma unroll
    for (int k = 0; k < NC; k++) {
        hin[k * NCH + ch] = h;
        h = Co[k * NCH + ch] * h + Vo[k * NCH + ch];
    }
    finals[ch] = h;
}

// pass 3: recompute with h_in; fp32 residual add; optional fp16 copy out.
__global__ __launch_bounds__(128) void scan3_kernel(
    const float* __restrict__ gh, const float* __restrict__ inp,
    const float* __restrict__ hin, float* __restrict__ outF,
    __half* __restrict__ o16)
{
    const int idx = blockIdx.x * blockDim.x + threadIdx.x;
    const int hh = idx & (HH - 1);
    const int rest = idx >> 10;
    const int chunk = rest & (NC - 1);
    const int b = rest >> 5;
    const int ch = b * HH + hh;

    const size_t base2h = (size_t)(b * SS + chunk * CS) * N2H + hh;
    const size_t base1h = (size_t)(b * SS + chunk * CS) * HH + hh;
    const float* g = gh + base2h;

    float h = hin[chunk * NCH + ch];
#pragma unroll 4
    for (int s = 0; s < CS; s++) {
        float c, d;
        gate_cd(g[(size_t)s * N2H], g[(size_t)s * N2H + HH], c, d);
        h = c * h + d;
        const size_t p = base1h + (size_t)s * HH;
        const float o = h + inp[p];
        outF[p] = o;
        if (o16) o16[p] = __float2half(o);
    }
}

// ---------------- launch ----------------
extern "C" void kernel_launch(void* const* d_in, const int* in_sizes, int n_in,
                              void* d_out, int out_size)
{
    const float* x  = (const float*)d_in[0];  // (B,S,D)
    const float* h0 = (const float*)d_in[1];  // (L,B,1,H)
    const float* W0 = (const float*)d_in[2];  // (2H,D)
    const float* b0 = (const float*)d_in[3];  // (2H,)
    const float* Wl = (const float*)d_in[4];  // (L-1,2H,H)
    const float* bl = (const float*)d_in[5];  // (L-1,2H)

    float* out    = (float*)d_out;
    float* finals = out + (size_t)MM * HH;

    float *gh, *act, *Cb, *Vb, *hinb;
    __half *af16, *w16;
    cudaGetSymbolAddress((void**)&gh,   g_gh);
    cudaGetSymbolAddress((void**)&act,  g_act);
    cudaGetSymbolAddress((void**)&af16, g_af16);
    cudaGetSymbolAddress((void**)&w16,  g_w16);
    cudaGetSymbolAddress((void**)&Cb,   g_C);
    cudaGetSymbolAddress((void**)&Vb,   g_V);
    cudaGetSymbolAddress((void**)&hinb, g_hin);

    cudaFuncSetAttribute(gemm_mma, cudaFuncAttributeMaxDynamicSharedMemorySize, SMEM_TOTAL);

    // x -> fp16; weights -> fp16 of 64*W
    {
        int n4 = (MM * KK) / 4;
        tof16_kernel<<<(n4 + 255) / 256, 256>>>((const float4*)x, (uint2*)af16, 1.0f, n4);
        n4 = (N2H * KK) / 4;
        tof16_kernel<<<(n4 + 255) / 256, 256>>>((const float4*)W0, (uint2*)w16, WSCALE, n4);
        n4 = (3 * N2H * KK) / 4;
        tof16_kernel<<<(n4 + 255) / 256, 256>>>((const float4*)Wl,
                                                (uint2*)(w16 + (size_t)N2H * KK), WSCALE, n4);
    }

    const dim3 ggrid(N2H / BN, MM / BM);           // (16, 128)
    const int scan13_blocks = (NCH * NC) / 128;    // 2048
    const int scan2_blocks = NCH / 128;            // 64

    for (int l = 0; l < LL; l++) {
        const __half* Wll = w16 + (size_t)l * N2H * KK;
        const float* bb = (l == 0) ? b0 : (bl + (size_t)(l - 1) * N2H);

        gemm_mma<<<ggrid, 256, SMEM_TOTAL>>>(af16, Wll, bb, gh);

        scan1_kernel<<<scan13_blocks, 128>>>(gh, Cb, Vb);
        scan2_kernel<<<scan2_blocks, 128>>>(Cb, Vb, h0 + (size_t)l * NCH, hinb,
                                            finals + (size_t)l * NCH);

        const float* inp = (l == 0) ? x : act;
        float* o = (l == LL - 1) ? out : act;
        scan3_kernel<<<scan13_blocks, 128>>>(gh, inp, hinb, o,
                                             (l == LL - 1) ? nullptr : af16);
    }
}

// round 11
// speedup vs baseline: 7.2460x; 1.0925x over previous
#include <cuda_runtime.h>
#include <cuda_bf16.h>
#include <cuda_fp16.h>
#include <cstdint>

// ---------------- problem dims ----------------
#define BB 8
#define SS 2048
#define HH 1024
#define LL 4
#define MM (BB * SS)       // 16384
#define N2H (2 * HH)       // 2048
#define KK 1024

// scan chunking
#define NC 32
#define CS (SS / NC)       // 64
#define NCH (BB * HH)      // 8192

// GEMM tiling
#define BM 128
#define BN 128
#define BK 64
#define NKIT (KK / BK)     // 16

#define MAT_B (BM * 128)                // 16384 bytes per tile (128B rows)
#define STAGE_B (2 * MAT_B)             // A, W = 32768
#define NSTAGE 3
#define SMEM_TOTAL (NSTAGE * STAGE_B)   // 98304 -> 2 CTAs/SM

// SW128 swizzle for 128B rows: XOR bits[6:4] with bits[9:7].
// Row deltas (multiples of 2048) commute with the swizzle; k-step deltas
// (+32/+64/+96) do NOT -> per-ks precomputed swizzled bases.
#define SWZ(off) ((off) ^ (((off) >> 3) & 0x70))

#define WSCALE 64.0f
#define WINV   0.015625f

// ---------------- scratch (device globals; allocation banned) ----------------
__device__ __half  g_gh  [(size_t)MM * N2H];    // fp16 gate|hidden
__device__ float   g_act [(size_t)MM * HH];     // fp32 residual stream
__device__ __half  g_af16[(size_t)MM * KK];     // fp16 GEMM copy of activations
__device__ __half  g_w16 [(size_t)LL * N2H * KK];
__device__ float   g_C   [(size_t)NC * NCH];
__device__ float   g_V   [(size_t)NC * NCH];
__device__ float   g_hin [(size_t)NC * NCH];

// ---------------- PTX helpers ----------------
__device__ __forceinline__ uint32_t smem_u32(const void* p) {
    uint32_t a;
    asm("{ .reg .u64 t; cvta.to.shared.u64 t, %1; cvt.u32.u64 %0, t; }"
        : "=r"(a) : "l"(p));
    return a;
}
__device__ __forceinline__ void cp16(uint32_t s, const void* g) {
    asm volatile("cp.async.cg.shared.global [%0], [%1], 16;" :: "r"(s), "l"(g));
}
__device__ __forceinline__ void cp_commit() {
    asm volatile("cp.async.commit_group;" ::: "memory");
}
template <int N>
__device__ __forceinline__ void cp_wait() {
    asm volatile("cp.async.wait_group %0;" :: "n"(N) : "memory");
}
__device__ __forceinline__ void ldsm4(uint32_t* r, uint32_t addr) {
    asm volatile("ldmatrix.sync.aligned.m8n8.x4.shared.b16 {%0,%1,%2,%3}, [%4];"
                 : "=r"(r[0]), "=r"(r[1]), "=r"(r[2]), "=r"(r[3]) : "r"(addr));
}
__device__ __forceinline__ void mma16816(float* c, const uint32_t* a, const uint32_t* b) {
    asm volatile(
        "mma.sync.aligned.m16n8k16.row.col.f32.f16.f16.f32 "
        "{%0,%1,%2,%3}, {%4,%5,%6,%7}, {%8,%9}, {%0,%1,%2,%3};"
        : "+f"(c[0]), "+f"(c[1]), "+f"(c[2]), "+f"(c[3])
        : "r"(a[0]), "r"(a[1]), "r"(a[2]), "r"(a[3]), "r"(b[0]), "r"(b[1]));
}

// ---------------- converts ----------------
__global__ __launch_bounds__(256) void tof16_kernel(
    const float4* __restrict__ in, uint2* __restrict__ o16, float scale, int n4)
{
    int i = blockIdx.x * blockDim.x + threadIdx.x;
    if (i >= n4) return;
    float4 v = in[i];
    uint2 H;
    H.x = (uint32_t)__half_as_ushort(__float2half(v.x * scale))
        | ((uint32_t)__half_as_ushort(__float2half(v.y * scale)) << 16);
    H.y = (uint32_t)__half_as_ushort(__float2half(v.z * scale))
        | ((uint32_t)__half_as_ushort(__float2half(v.w * scale)) << 16);
    o16[i] = H;
}

// ---------------- mma.sync GEMM: gh = fp16((A * (64W)^T)/64 + bias) ----------
// A fp16 (M,K); W fp16 (N,K) pre-scaled by 64. CTA 128x128, BK=64, 8 warps
// (4M x 2N), warp tile 32x64, 3-stage cp.async ring, 64 MMAs per barrier.
__global__ __launch_bounds__(256, 2) void gemm_mma(
    const __half* __restrict__ Af, const __half* __restrict__ Wf,
    const float* __restrict__ bias, __half* __restrict__ C)
{
    extern __shared__ __align__(1024) char smem[];
    const uint32_t sbase = smem_u32(smem);

    const int tid = threadIdx.x;
    const int wid = tid >> 5;
    const int lane = tid & 31;
    const int wm = wid & 3;
    const int wn = wid >> 2;
    const int row0 = blockIdx.y * BM;
    const int col0 = blockIdx.x * BN;

    // loader: tile = 128 rows x 128B = 1024 x 16B chunks; 4 per thread per tile
    uint32_t so[4]; size_t go[4];
#pragma unroll
    for (int j = 0; j < 4; j++) {
        const int i = tid + 256 * j;
        const int r = i >> 3, c = i & 7;
        so[j] = SWZ((uint32_t)(r * 128 + c * 16));
        go[j] = (size_t)r * KK + c * 8;
    }

    const __half* Ap = Af + (size_t)row0 * KK;
    const __half* Wp = Wf + (size_t)col0 * KK;

    auto load_stage = [&](int kt, int s) {
        const uint32_t st = sbase + s * STAGE_B;
        const int kof = kt * BK;
#pragma unroll
        for (int j = 0; j < 4; j++) {
            cp16(st + so[j],         Ap + go[j] + kof);
            cp16(st + MAT_B + so[j], Wp + go[j] + kof);
        }
        cp_commit();
    };

    float acc[2][8][4];
#pragma unroll
    for (int t = 0; t < 2; t++)
#pragma unroll
        for (int n = 0; n < 8; n++)
#pragma unroll
            for (int q = 0; q < 4; q++) acc[t][n][q] = 0.0f;

    // per-lane swizzled fragment bases, one per k16 step (4 per kt)
    const int arow = ((lane >> 3) & 1) * 8 + (lane & 7);
    const int akof = (lane >> 4) * 16;
    const int brow = ((lane >> 4) & 1) * 8 + (lane & 7);
    const int bkof = ((lane >> 3) & 1) * 16;
    const uint32_t araw = (uint32_t)((wm * 32 + arow) * 128 + akof);
    const uint32_t braw = (uint32_t)((wn * 64 + brow) * 128 + bkof);
    uint32_t aswz[4], bswz[4];
#pragma unroll
    for (int ks = 0; ks < 4; ks++) {
        aswz[ks] = SWZ(araw + ks * 32);
        bswz[ks] = SWZ(braw + ks * 32);
    }

    load_stage(0, 0);
    load_stage(1, 1);

    for (int kt = 0; kt < NKIT; kt++) {
        cp_wait<1>();
        __syncthreads();

        if (kt + 2 < NKIT) {
            int s = kt + 2; while (s >= NSTAGE) s -= NSTAGE;
            load_stage(kt + 2, s);
        }

        int cs = kt; while (cs >= NSTAGE) cs -= NSTAGE;
        const uint32_t stg = sbase + cs * STAGE_B;
        const uint32_t wbs = stg + MAT_B;

        uint32_t ah[2][2][4], bf[2][4];

        ldsm4(ah[0][0], stg + aswz[0]);
        ldsm4(ah[0][1], stg + aswz[0] + 2048);
        ldsm4(bf[0], wbs + bswz[0]);

#pragma unroll
        for (int ks = 0; ks < 4; ks++) {
#pragma unroll
            for (int p = 0; p < 4; p++) {
                // next B fragment (rolling into next ks at the seam)
                if (p < 3)        ldsm4(bf[(p + 1) & 1], wbs + bswz[ks] + (p + 1) * 2048);
                else if (ks < 3)  ldsm4(bf[(p + 1) & 1], wbs + bswz[ks + 1]);
                // next ks A fragments, early
                if (ks < 3 && p == 0) ldsm4(ah[(ks + 1) & 1][0], stg + aswz[ks + 1]);
                if (ks < 3 && p == 1) ldsm4(ah[(ks + 1) & 1][1], stg + aswz[ks + 1] + 2048);
                const uint32_t* r4 = bf[p & 1];
#pragma unroll
                for (int t = 0; t < 2; t++) {
                    mma16816(acc[t][2 * p],     ah[ks & 1][t], r4);
                    mma16816(acc[t][2 * p + 1], ah[ks & 1][t], r4 + 2);
                }
            }
        }
    }

    // epilogue: scale, bias, convert to fp16, store half2 pairs
    const int erow = row0 + wm * 32 + (lane >> 2);
    const int ecol0 = col0 + wn * 64 + 2 * (lane & 3);
#pragma unroll
    for (int t = 0; t < 2; t++) {
#pragma unroll
        for (int n = 0; n < 8; n++) {
            const int col = ecol0 + n * 8;
            const float2 bv = *(const float2*)(bias + col);
            __half2 h0 = __floats2half2_rn(fmaf(acc[t][n][0], WINV, bv.x),
                                           fmaf(acc[t][n][1], WINV, bv.y));
            __half2 h1 = __floats2half2_rn(fmaf(acc[t][n][2], WINV, bv.x),
                                           fmaf(acc[t][n][3], WINV, bv.y));
            *(__half2*)(C + (size_t)(erow + t * 16) * N2H + col) = h0;
            *(__half2*)(C + (size_t)(erow + t * 16 + 8) * N2H + col) = h1;
        }
    }
}

// ---------------- scan ----------------
__device__ __forceinline__ void gate_cd(float gate, float hid, float& c, float& d) {
    const float t = __expf(-gate);
    const float inv = __fdividef(1.0f, 1.0f + t);
    c = t * inv;                  // 1 - sigmoid(gate)
    const float gx = (hid >= 0.0f) ? (hid + 0.5f)
                                   : __fdividef(1.0f, 1.0f + __expf(-hid));
    d = inv * gx;                 // sigmoid(gate) * g(hid)
}

__global__ __launch_bounds__(128) void scan1_kernel(
    const __half* __restrict__ gh, float* __restrict__ Co, float* __restrict__ Vo)
{
    const int idx = blockIdx.x * blockDim.x + threadIdx.x;
    const int hh = idx & (HH - 1);
    const int rest = idx >> 10;
    const int chunk = rest & (NC - 1);
    const int b = rest >> 5;

    const __half* g = gh + (size_t)(b * SS + chunk * CS) * N2H + hh;
    float Ca = 1.0f, Va = 0.0f;
#pragma unroll 4
    for (int s = 0; s < CS; s++) {
        float c, d;
        gate_cd(__half2float(g[(size_t)s * N2H]),
                __half2float(g[(size_t)s * N2H + HH]), c, d);
        Ca *= c;
        Va = c * Va + d;
    }
    const int ch = b * HH + hh;
    Co[chunk * NCH + ch] = Ca;
    Vo[chunk * NCH + ch] = Va;
}

__global__ __launch_bounds__(128) void scan2_kernel(
    const float* __restrict__ Co, const float* __restrict__ Vo,
    const float* __restrict__ hprev, float* __restrict__ hin,
    float* __restrict__ finals)
{
    const int ch = blockIdx.x * blockDim.x + threadIdx.x;
    const float hp = hprev[ch];
    float h = (hp >= 0.0f) ? (hp + 0.5f) : __fdividef(1.0f, 1.0f + __expf(-hp));
#pragma unroll
    for (int k = 0; k < NC; k++) {
        hin[k * NCH + ch] = h;
        h = Co[k * NCH + ch] * h + Vo[k * NCH + ch];
    }
    finals[ch] = h;
}

// pass 3: recompute with h_in; fp32 residual add; optional fp16 copy out.
__global__ __launch_bounds__(128) void scan3_kernel(
    const __half* __restrict__ gh, const float* __restrict__ inp,
    const float* __restrict__ hin, float* __restrict__ outF,
    __half* __restrict__ o16)
{
    const int idx = blockIdx.x * blockDim.x + threadIdx.x;
    const int hh = idx & (HH - 1);
    const int rest = idx >> 10;
    const int chunk = rest & (NC - 1);
    const int b = rest >> 5;
    const int ch = b * HH + hh;

    const size_t base2h = (size_t)(b * SS + chunk * CS) * N2H + hh;
    const size_t base1h = (size_t)(b * SS + chunk * CS) * HH + hh;
    const __half* g = gh + base2h;

    float h = hin[chunk * NCH + ch];
#pragma unroll 4
    for (int s = 0; s < CS; s++) {
        float c, d;
        gate_cd(__half2float(g[(size_t)s * N2H]),
                __half2float(g[(size_t)s * N2H + HH]), c, d);
        h = c * h + d;
        const size_t p = base1h + (size_t)s * HH;
        const float o = h + inp[p];
        outF[p] = o;
        if (o16) o16[p] = __float2half(o);
    }
}

// ---------------- launch ----------------
extern "C" void kernel_launch(void* const* d_in, const int* in_sizes, int n_in,
                              void* d_out, int out_size)
{
    const float* x  = (const float*)d_in[0];  // (B,S,D)
    const float* h0 = (const float*)d_in[1];  // (L,B,1,H)
    const float* W0 = (const float*)d_in[2];  // (2H,D)
    const float* b0 = (const float*)d_in[3];  // (2H,)
    const float* Wl = (const float*)d_in[4];  // (L-1,2H,H)
    const float* bl = (const float*)d_in[5];  // (L-1,2H)

    float* out    = (float*)d_out;
    float* finals = out + (size_t)MM * HH;

    float *act, *Cb, *Vb, *hinb;
    __half *gh, *af16, *w16;
    cudaGetSymbolAddress((void**)&gh,   g_gh);
    cudaGetSymbolAddress((void**)&act,  g_act);
    cudaGetSymbolAddress((void**)&af16, g_af16);
    cudaGetSymbolAddress((void**)&w16,  g_w16);
    cudaGetSymbolAddress((void**)&Cb,   g_C);
    cudaGetSymbolAddress((void**)&Vb,   g_V);
    cudaGetSymbolAddress((void**)&hinb, g_hin);

    cudaFuncSetAttribute(gemm_mma, cudaFuncAttributeMaxDynamicSharedMemorySize, SMEM_TOTAL);

    // x -> fp16; weights -> fp16 of 64*W
    {
        int n4 = (MM * KK) / 4;
        tof16_kernel<<<(n4 + 255) / 256, 256>>>((const float4*)x, (uint2*)af16, 1.0f, n4);
        n4 = (N2H * KK) / 4;
        tof16_kernel<<<(n4 + 255) / 256, 256>>>((const float4*)W0, (uint2*)w16, WSCALE, n4);
        n4 = (3 * N2H * KK) / 4;
        tof16_kernel<<<(n4 + 255) / 256, 256>>>((const float4*)Wl,
                                                (uint2*)(w16 + (size_t)N2H * KK), WSCALE, n4);
    }

    const dim3 ggrid(N2H / BN, MM / BM);           // (16, 128)
    const int scan13_blocks = (NCH * NC) / 128;    // 2048
    const int scan2_blocks = NCH / 128;            // 64

    for (int l = 0; l < LL; l++) {
        const __half* Wll = w16 + (size_t)l * N2H * KK;
        const float* bb = (l == 0) ? b0 : (bl + (size_t)(l - 1) * N2H);

        gemm_mma<<<ggrid, 256, SMEM_TOTAL>>>(af16, Wll, bb, gh);

        scan1_kernel<<<scan13_blocks, 128>>>(gh, Cb, Vb);
        scan2_kernel<<<scan2_blocks, 128>>>(Cb, Vb, h0 + (size_t)l * NCH, hinb,
                                            finals + (size_t)l * NCH);

        const float* inp = (l == 0) ? x : act;
        float* o = (l == LL - 1) ? out : act;
        scan3_kernel<<<scan13_blocks, 128>>>(gh, inp, hinb, o,
                                             (l == LL - 1) ? nullptr : af16);
    }
}

// round 12
// speedup vs baseline: 7.4380x; 1.0265x over previous
#include <cuda_runtime.h>
#include <cuda_bf16.h>
#include <cuda_fp16.h>
#include <cstdint>

// ---------------- problem dims ----------------
#define BB 8
#define SS 2048
#define HH 1024
#define LL 4
#define MM (BB * SS)       // 16384
#define N2H (2 * HH)       // 2048
#define KK 1024

// scan chunking
#define NC 32
#define CS (SS / NC)       // 64
#define NCH (BB * HH)      // 8192

// GEMM tiling
#define BM 128
#define BN 128
#define BK 64
#define NKIT (KK / BK)     // 16

#define MAT_B (BM * 128)                // 16384 bytes per tile (128B rows)
#define STAGE_B (2 * MAT_B)             // A, W = 32768
#define NSTAGE 3
#define SMEM_TOTAL (NSTAGE * STAGE_B)   // 98304 -> 2 CTAs/SM

// SW128 swizzle for 128B rows: XOR bits[6:4] with bits[9:7].
// Row deltas (multiples of 2048) commute; k-step deltas do NOT.
#define SWZ(off) ((off) ^ (((off) >> 3) & 0x70))

#define WSCALE 64.0f
#define WINV   0.015625f

// ---------------- scratch (device globals; allocation banned) ----------------
__device__ __half  g_gh  [(size_t)MM * N2H];    // fp16 gate|hidden
__device__ __half  g_ahi [(size_t)MM * KK];     // residual hi (GEMM operand)
__device__ __half  g_alo [(size_t)MM * KK];     // residual lo
__device__ __half  g_w16 [(size_t)LL * N2H * KK];
__device__ float   g_C   [(size_t)NC * NCH];
__device__ float   g_V   [(size_t)NC * NCH];
__device__ float   g_hin [(size_t)NC * NCH];

// ---------------- PTX helpers ----------------
__device__ __forceinline__ uint32_t smem_u32(const void* p) {
    uint32_t a;
    asm("{ .reg .u64 t; cvta.to.shared.u64 t, %1; cvt.u32.u64 %0, t; }"
        : "=r"(a) : "l"(p));
    return a;
}
__device__ __forceinline__ void cp16(uint32_t s, const void* g) {
    asm volatile("cp.async.cg.shared.global [%0], [%1], 16;" :: "r"(s), "l"(g));
}
__device__ __forceinline__ void cp_commit() {
    asm volatile("cp.async.commit_group;" ::: "memory");
}
template <int N>
__device__ __forceinline__ void cp_wait() {
    asm volatile("cp.async.wait_group %0;" :: "n"(N) : "memory");
}
__device__ __forceinline__ void ldsm4(uint32_t* r, uint32_t addr) {
    asm volatile("ldmatrix.sync.aligned.m8n8.x4.shared.b16 {%0,%1,%2,%3}, [%4];"
                 : "=r"(r[0]), "=r"(r[1]), "=r"(r[2]), "=r"(r[3]) : "r"(addr));
}
__device__ __forceinline__ void mma16816(float* c, const uint32_t* a, const uint32_t* b) {
    asm volatile(
        "mma.sync.aligned.m16n8k16.row.col.f32.f16.f16.f32 "
        "{%0,%1,%2,%3}, {%4,%5,%6,%7}, {%8,%9}, {%0,%1,%2,%3};"
        : "+f"(c[0]), "+f"(c[1]), "+f"(c[2]), "+f"(c[3])
        : "r"(a[0]), "r"(a[1]), "r"(a[2]), "r"(a[3]), "r"(b[0]), "r"(b[1]));
}

// ---------------- converts ----------------
__global__ __launch_bounds__(256) void tof16_kernel(
    const float4* __restrict__ in, uint2* __restrict__ o16, float scale, int n4)
{
    int i = blockIdx.x * blockDim.x + threadIdx.x;
    if (i >= n4) return;
    float4 v = in[i];
    uint2 H;
    H.x = (uint32_t)__half_as_ushort(__float2half(v.x * scale))
        | ((uint32_t)__half_as_ushort(__float2half(v.y * scale)) << 16);
    H.y = (uint32_t)__half_as_ushort(__float2half(v.z * scale))
        | ((uint32_t)__half_as_ushort(__float2half(v.w * scale)) << 16);
    o16[i] = H;
}

// ---------------- mma.sync GEMM: gh = fp16((A * (64W)^T)/64 + bias) ----------
// A fp16 (M,K); W fp16 (N,K) pre-scaled by 64. CTA 128x128, BK=64, 8 warps
// (4M x 2N), warp tile 32x64, 3-stage cp.async ring, 64 MMAs per barrier.
// Post-barrier: ldsm first, cp.async after (tensor pipe restarts earlier).
__global__ __launch_bounds__(256, 2) void gemm_mma(
    const __half* __restrict__ Af, const __half* __restrict__ Wf,
    const float* __restrict__ bias, __half* __restrict__ C)
{
    extern __shared__ __align__(1024) char smem[];
    const uint32_t sbase = smem_u32(smem);

    const int tid = threadIdx.x;
    const int wid = tid >> 5;
    const int lane = tid & 31;
    const int wm = wid & 3;
    const int wn = wid >> 2;
    const int row0 = blockIdx.y * BM;
    const int col0 = blockIdx.x * BN;

    // loader: tile = 128 rows x 128B = 1024 x 16B chunks; 4 per thread per tile
    uint32_t so[4]; size_t go[4];
#pragma unroll
    for (int j = 0; j < 4; j++) {
        const int i = tid + 256 * j;
        const int r = i >> 3, c = i & 7;
        so[j] = SWZ((uint32_t)(r * 128 + c * 16));
        go[j] = (size_t)r * KK + c * 8;
    }

    const __half* Ap = Af + (size_t)row0 * KK;
    const __half* Wp = Wf + (size_t)col0 * KK;

    auto load_stage = [&](int kt, int s) {
        const uint32_t st = sbase + s * STAGE_B;
        const int kof = kt * BK;
#pragma unroll
        for (int j = 0; j < 4; j++) {
            cp16(st + so[j],         Ap + go[j] + kof);
            cp16(st + MAT_B + so[j], Wp + go[j] + kof);
        }
        cp_commit();
    };

    float acc[2][8][4];
#pragma unroll
    for (int t = 0; t < 2; t++)
#pragma unroll
        for (int n = 0; n < 8; n++)
#pragma unroll
            for (int q = 0; q < 4; q++) acc[t][n][q] = 0.0f;

    // per-lane swizzled fragment bases, one per k16 step (4 per kt)
    const int arow = ((lane >> 3) & 1) * 8 + (lane & 7);
    const int akof = (lane >> 4) * 16;
    const int brow = ((lane >> 4) & 1) * 8 + (lane & 7);
    const int bkof = ((lane >> 3) & 1) * 16;
    const uint32_t araw = (uint32_t)((wm * 32 + arow) * 128 + akof);
    const uint32_t braw = (uint32_t)((wn * 64 + brow) * 128 + bkof);
    uint32_t aswz[4], bswz[4];
#pragma unroll
    for (int ks = 0; ks < 4; ks++) {
        aswz[ks] = SWZ(araw + ks * 32);
        bswz[ks] = SWZ(braw + ks * 32);
    }

    load_stage(0, 0);
    load_stage(1, 1);

    int cs = 0, ls = 2;   // consume stage, load stage (incremental ring counters)
    for (int kt = 0; kt < NKIT; kt++) {
        cp_wait<1>();
        __syncthreads();

        const uint32_t stg = sbase + cs * STAGE_B;
        const uint32_t wbs = stg + MAT_B;
        if (++cs == NSTAGE) cs = 0;

        uint32_t ah[2][2][4], bf[2][4];

        // ldsm burst first so the tensor pipe restarts ASAP...
        ldsm4(ah[0][0], stg + aswz[0]);
        ldsm4(ah[0][1], stg + aswz[0] + 2048);
        ldsm4(bf[0], wbs + bswz[0]);

        // ...then the global->smem prefetch for kt+2
        if (kt + 2 < NKIT) {
            load_stage(kt + 2, ls);
            if (++ls == NSTAGE) ls = 0;
        }

#pragma unroll
        for (int ks = 0; ks < 4; ks++) {
#pragma unroll
            for (int p = 0; p < 4; p++) {
                if (p < 3)        ldsm4(bf[(p + 1) & 1], wbs + bswz[ks] + (p + 1) * 2048);
                else if (ks < 3)  ldsm4(bf[(p + 1) & 1], wbs + bswz[ks + 1]);
                if (ks < 3 && p == 0) ldsm4(ah[(ks + 1) & 1][0], stg + aswz[ks + 1]);
                if (ks < 3 && p == 1) ldsm4(ah[(ks + 1) & 1][1], stg + aswz[ks + 1] + 2048);
                const uint32_t* r4 = bf[p & 1];
#pragma unroll
                for (int t = 0; t < 2; t++) {
                    mma16816(acc[t][2 * p],     ah[ks & 1][t], r4);
                    mma16816(acc[t][2 * p + 1], ah[ks & 1][t], r4 + 2);
                }
            }
        }
    }

    // epilogue: scale, bias, convert to fp16, store half2 pairs
    const int erow = row0 + wm * 32 + (lane >> 2);
    const int ecol0 = col0 + wn * 64 + 2 * (lane & 3);
#pragma unroll
    for (int t = 0; t < 2; t++) {
#pragma unroll
        for (int n = 0; n < 8; n++) {
            const int col = ecol0 + n * 8;
            const float2 bv = *(const float2*)(bias + col);
            __half2 h0 = __floats2half2_rn(fmaf(acc[t][n][0], WINV, bv.x),
                                           fmaf(acc[t][n][1], WINV, bv.y));
            __half2 h1 = __floats2half2_rn(fmaf(acc[t][n][2], WINV, bv.x),
                                           fmaf(acc[t][n][3], WINV, bv.y));
            *(__half2*)(C + (size_t)(erow + t * 16) * N2H + col) = h0;
            *(__half2*)(C + (size_t)(erow + t * 16 + 8) * N2H + col) = h1;
        }
    }
}

// ---------------- scan ----------------
__device__ __forceinline__ void gate_cd(float gate, float hid, float& c, float& d) {
    const float t = __expf(-gate);
    const float inv = __fdividef(1.0f, 1.0f + t);
    c = t * inv;                  // 1 - sigmoid(gate)
    const float gx = (hid >= 0.0f) ? (hid + 0.5f)
                                   : __fdividef(1.0f, 1.0f + __expf(-hid));
    d = inv * gx;                 // sigmoid(gate) * g(hid)
}

__global__ __launch_bounds__(128) void scan1_kernel(
    const __half* __restrict__ gh, float* __restrict__ Co, float* __restrict__ Vo)
{
    const int idx = blockIdx.x * blockDim.x + threadIdx.x;
    const int hh = idx & (HH - 1);
    const int rest = idx >> 10;
    const int chunk = rest & (NC - 1);
    const int b = rest >> 5;

    const __half* g = gh + (size_t)(b * SS + chunk * CS) * N2H + hh;
    float Ca = 1.0f, Va = 0.0f;
#pragma unroll 4
    for (int s = 0; s < CS; s++) {
        float c, d;
        gate_cd(__half2float(g[(size_t)s * N2H]),
                __half2float(g[(size_t)s * N2H + HH]), c, d);
        Ca *= c;
        Va = c * Va + d;
    }
    const int ch = b * HH + hh;
    Co[chunk * NCH + ch] = Ca;
    Vo[chunk * NCH + ch] = Va;
}

__global__ __launch_bounds__(128) void scan2_kernel(
    const float* __restrict__ Co, const float* __restrict__ Vo,
    const float* __restrict__ hprev, float* __restrict__ hin,
    float* __restrict__ finals)
{
    const int ch = blockIdx.x * blockDim.x + threadIdx.x;
    const float hp = hprev[ch];
    float h = (hp >= 0.0f) ? (hp + 0.5f) : __fdividef(1.0f, 1.0f + __expf(-hp));
#pragma unroll
    for (int k = 0; k < NC; k++) {
        hin[k * NCH + ch] = h;
        h = Co[k * NCH + ch] * h + Vo[k * NCH + ch];
    }
    finals[ch] = h;
}

// pass 3: recompute with h_in; residual = fp16 hi/lo pair (x = hi+lo, exact to
// 2^-22); layer0 reads fp32 x; last layer writes fp32 out, others update the
// hi/lo pair in place (hi is the next GEMM's A operand).
__global__ __launch_bounds__(128) void scan3_kernel(
    const __half* __restrict__ gh, const float* __restrict__ inpF,
    __half* __restrict__ ihi, __half* __restrict__ ilo,
    const float* __restrict__ hin, float* __restrict__ outF)
{
    const int idx = blockIdx.x * blockDim.x + threadIdx.x;
    const int hh = idx & (HH - 1);
    const int rest = idx >> 10;
    const int chunk = rest & (NC - 1);
    const int b = rest >> 5;
    const int ch = b * HH + hh;

    const size_t base2h = (size_t)(b * SS + chunk * CS) * N2H + hh;
    const size_t base1h = (size_t)(b * SS + chunk * CS) * HH + hh;
    const __half* g = gh + base2h;

    float h = hin[chunk * NCH + ch];
#pragma unroll 4
    for (int s = 0; s < CS; s++) {
        float c, d;
        gate_cd(__half2float(g[(size_t)s * N2H]),
                __half2float(g[(size_t)s * N2H + HH]), c, d);
        h = c * h + d;
        const size_t p = base1h + (size_t)s * HH;
        const float xin = inpF ? inpF[p]
                               : (__half2float(ihi[p]) + __half2float(ilo[p]));
        const float o = h + xin;
        if (outF) {
            outF[p] = o;
        } else {
            const __half hb = __float2half(o);
            ihi[p] = hb;
            ilo[p] = __float2half(o - __half2float(hb));
        }
    }
}

// ---------------- launch ----------------
extern "C" void kernel_launch(void* const* d_in, const int* in_sizes, int n_in,
                              void* d_out, int out_size)
{
    const float* x  = (const float*)d_in[0];  // (B,S,D)
    const float* h0 = (const float*)d_in[1];  // (L,B,1,H)
    const float* W0 = (const float*)d_in[2];  // (2H,D)
    const float* b0 = (const float*)d_in[3];  // (2H,)
    const float* Wl = (const float*)d_in[4];  // (L-1,2H,H)
    const float* bl = (const float*)d_in[5];  // (L-1,2H)

    float* out    = (float*)d_out;
    float* finals = out + (size_t)MM * HH;

    float *Cb, *Vb, *hinb;
    __half *gh, *ahi, *alo, *w16;
    cudaGetSymbolAddress((void**)&gh,   g_gh);
    cudaGetSymbolAddress((void**)&ahi,  g_ahi);
    cudaGetSymbolAddress((void**)&alo,  g_alo);
    cudaGetSymbolAddress((void**)&w16,  g_w16);
    cudaGetSymbolAddress((void**)&Cb,   g_C);
    cudaGetSymbolAddress((void**)&Vb,   g_V);
    cudaGetSymbolAddress((void**)&hinb, g_hin);

    cudaFuncSetAttribute(gemm_mma, cudaFuncAttributeMaxDynamicSharedMemorySize, SMEM_TOTAL);

    // x -> fp16 (GEMM operand only; layer0 residual reads fp32 x directly);
    // weights -> fp16 of 64*W
    {
        int n4 = (MM * KK) / 4;
        tof16_kernel<<<(n4 + 255) / 256, 256>>>((const float4*)x, (uint2*)ahi, 1.0f, n4);
        n4 = (N2H * KK) / 4;
        tof16_kernel<<<(n4 + 255) / 256, 256>>>((const float4*)W0, (uint2*)w16, WSCALE, n4);
        n4 = (3 * N2H * KK) / 4;
        tof16_kernel<<<(n4 + 255) / 256, 256>>>((const float4*)Wl,
                                                (uint2*)(w16 + (size_t)N2H * KK), WSCALE, n4);
    }

    const dim3 ggrid(N2H / BN, MM / BM);           // (16, 128)
    const int scan13_blocks = (NCH * NC) / 128;    // 2048
    const int scan2_blocks = NCH / 128;            // 64

    for (int l = 0; l < LL; l++) {
        const __half* Wll = w16 + (size_t)l * N2H * KK;
        const float* bb = (l == 0) ? b0 : (bl + (size_t)(l - 1) * N2H);

        gemm_mma<<<ggrid, 256, SMEM_TOTAL>>>(ahi, Wll, bb, gh);

        scan1_kernel<<<scan13_blocks, 128>>>(gh, Cb, Vb);
        scan2_kernel<<<scan2_blocks, 128>>>(Cb, Vb, h0 + (size_t)l * NCH, hinb,
                                            finals + (size_t)l * NCH);

        scan3_kernel<<<scan13_blocks, 128>>>(gh, (l == 0) ? x : nullptr,
                                             ahi, alo, hinb,
                                             (l == LL - 1) ? out : nullptr);
    }
}